// round 13
// baseline (speedup 1.0000x reference)
#include <cuda_runtime.h>
#include <cuda_bf16.h>
#include <cuda_fp8.h>
#include <stdint.h>
#include <math.h>

#define BB 32
#define TT 64
#define VV 8000
#define EE 256
#define HH 512
#define GG 2048
#define WW 3
#define NEGF (-1e30f)
#define NDROW 4096
#define ROWS_E 64
#define PDT 68
#define PDROWS (PDT*BB)      // 2176
#define NP 250               // vocab partial strips of 32
#define SR (4*NDROW)

typedef __nv_bfloat16 bf16;

// ----- scratch -----
__device__ float d_Xe[TT*ROWS_E*GG];
__device__ float d_Pd[2*PDROWS*GG];
__device__ float d_Cdec[2*NDROW*HH];
__device__ int   d_tokE[TT*ROWS_E];
__device__ int   d_tokD[2*PDROWS];
__device__ float d_zc[3*NDROW];
__device__ float d_zt[4*NDROW];
__device__ float d_part[NP*SR*2];
__device__ float d_lse[4*NDROW];
__device__ float d_res[2*TT*WW*BB];
__device__ unsigned g_cnt;
__device__ unsigned g_gen;

// ----- bf16 mirrors -----
__device__ bf16 d_embB[VV*EE];
__device__ bf16 d_WeIB[GG*EE];
__device__ bf16 d_WfIB[GG*EE];
__device__ bf16 d_WbIB[GG*EE];
__device__ bf16 d_WfHB[GG*HH];
__device__ bf16 d_WbHB[GG*HH];
__device__ bf16 d_hWfB[VV*HH];
__device__ bf16 d_hWbB[VV*HH];
__device__ bf16 d_HencB[2*(TT+1)*BB*HH];
__device__ bf16 d_HdecB[5*NDROW*HH];

// ----- fp8 mirrors (vocab LSE path) -----
__device__ unsigned char d_hWf8[VV*HH];
__device__ unsigned char d_hWb8[VV*HH];
__device__ unsigned char d_Hd8[5*NDROW*HH];

__device__ __forceinline__ float sigm(float x){ return 1.f/(1.f+__expf(-x)); }
__device__ __forceinline__ unsigned sptr(const void* p){
    return (unsigned)__cvta_generic_to_shared(p);
}
__device__ __forceinline__ void ldsm4(unsigned* r, unsigned a){
    asm volatile("ldmatrix.sync.aligned.m8n8.x4.shared.b16 {%0,%1,%2,%3}, [%4];\n"
        : "=r"(r[0]),"=r"(r[1]),"=r"(r[2]),"=r"(r[3]) : "r"(a));
}
__device__ __forceinline__ void mma16(float* c, const unsigned* a, const unsigned* b){
    asm volatile("mma.sync.aligned.m16n8k16.row.col.f32.bf16.bf16.f32 "
        "{%0,%1,%2,%3},{%4,%5,%6,%7},{%8,%9},{%0,%1,%2,%3};\n"
        : "+f"(c[0]),"+f"(c[1]),"+f"(c[2]),"+f"(c[3])
        : "r"(a[0]),"r"(a[1]),"r"(a[2]),"r"(a[3]),"r"(b[0]),"r"(b[1]));
}
__device__ __forceinline__ void mma8f8(float* c, const unsigned* a, const unsigned* b){
    asm volatile("mma.sync.aligned.m16n8k32.row.col.f32.e4m3.e4m3.f32 "
        "{%0,%1,%2,%3},{%4,%5,%6,%7},{%8,%9},{%0,%1,%2,%3};\n"
        : "+f"(c[0]),"+f"(c[1]),"+f"(c[2]),"+f"(c[3])
        : "r"(a[0]),"r"(a[1]),"r"(a[2]),"r"(a[3]),"r"(b[0]),"r"(b[1]));
}
__device__ __forceinline__ void cp16(unsigned dst, const void* src, int ssz){
    asm volatile("cp.async.cg.shared.global [%0], [%1], 16, %2;\n"
        :: "r"(dst), "l"(src), "r"(ssz));
}
__device__ __forceinline__ unsigned char to8(float v){
    return (unsigned char)__nv_cvt_float_to_fp8(v, __NV_SATFINITE, __NV_E4M3);
}

// ----- fp32 -> bf16 conversion (2 merged kernels) -----
__global__ void k_convA(const float* __restrict__ emb, const float* __restrict__ eWih,
                        const float* __restrict__ fWih, const float* __restrict__ bWih){
    const long n0 = (long)VV*EE, n1 = n0 + (long)GG*EE, n2 = n1 + (long)GG*EE, n3 = n2 + (long)GG*EE;
    long i = ((long)blockIdx.x*blockDim.x + threadIdx.x)*4;
    if (i >= n3) return;
    const float* src; bf16* dst; long off;
    if (i < n0){ src=emb; dst=d_embB; off=i; }
    else if (i < n1){ src=eWih; dst=d_WeIB; off=i-n0; }
    else if (i < n2){ src=fWih; dst=d_WfIB; off=i-n1; }
    else { src=bWih; dst=d_WbIB; off=i-n2; }
    float4 v = *(const float4*)(src+off);
    *(__nv_bfloat162*)(dst+off)   = __floats2bfloat162_rn(v.x, v.y);
    *(__nv_bfloat162*)(dst+off+2) = __floats2bfloat162_rn(v.z, v.w);
}
__global__ void k_convB(const float* __restrict__ fWhh, const float* __restrict__ bWhh,
                        const float* __restrict__ fhW, const float* __restrict__ bhW){
    const long n0 = (long)GG*HH, n1 = n0 + (long)GG*HH, n2 = n1 + (long)VV*HH, n3 = n2 + (long)VV*HH;
    long i = ((long)blockIdx.x*blockDim.x + threadIdx.x)*4;
    if (i >= n3) return;
    const float* src; bf16* dst; long off;
    if (i < n0){ src=fWhh; dst=d_WfHB; off=i; }
    else if (i < n1){ src=bWhh; dst=d_WbHB; off=i-n0; }
    else if (i < n2){ src=fhW; dst=d_hWfB; off=i-n1; }
    else { src=bhW; dst=d_hWbB; off=i-n2; }
    float4 v = *(const float4*)(src+off);
    *(__nv_bfloat162*)(dst+off)   = __floats2bfloat162_rn(v.x, v.y);
    *(__nv_bfloat162*)(dst+off+2) = __floats2bfloat162_rn(v.z, v.w);
}
// ----- fp32 -> fp8 vocab weights -----
__global__ void k_conv8(const float* __restrict__ fhW, const float* __restrict__ bhW){
    const long n0 = (long)VV*HH;
    long i = ((long)blockIdx.x*blockDim.x + threadIdx.x)*4;
    if (i >= 2*n0) return;
    const float* src = (i < n0)? fhW : bhW;
    unsigned char* dst = (i < n0)? d_hWf8 : d_hWb8;
    long off = (i < n0)? i : i-n0;
    float4 v = *(const float4*)(src+off);
    dst[off]   = to8(v.x); dst[off+1] = to8(v.y);
    dst[off+2] = to8(v.z); dst[off+3] = to8(v.w);
}

// ----- init -----
__global__ void k_init(const int* __restrict__ sent){
    int i = blockIdx.x*blockDim.x + threadIdx.x;
    if (i == 0){ g_cnt = 0u; g_gen = 0u; }
    if (i < 2*BB*HH){
        int dir = i/(BB*HH); int rem = i%(BB*HH);
        d_HencB[(dir*(TT+1))*BB*HH + rem] = __float2bfloat16(0.f);
    }
    if (i < TT*ROWS_E){
        int t = i/ROWS_E, r = i%ROWS_E, dir = r/BB, b = r%BB;
        int tok = (t==0) ? 0 : (dir ? sent[b*TT + (TT-t)] : sent[b*TT + (t-1)]);
        d_tokE[i] = tok;
    }
    if (i < 2*PDROWS){
        int dir = i/PDROWS; int rem = i%PDROWS; int t = rem/BB, b = rem%BB;
        int tok = (t < TT) ? (dir ? sent[b*TT + (TT-1-t)] : sent[b*TT + t]) : 0;
        d_tokD[i] = tok;
    }
}

// ===================== bf16 mma.sync GEMM: 512 threads, 16 warps, warp-tile 32x32 =====================
// MODE 0: A=embB[tok], K=256, out Xe/Pd (+bias)
// MODE 1: A=HdecB[s],  K=512, gate-interleaved B rows; epilogue = fused LSTM cell (+fp8 quant)
#define BG_SMEM (6*5120*2)     // 61440 bytes
extern __shared__ bf16 dynsm[];

template<int MODE>
__global__ void __launch_bounds__(512,2) k_bgemm(
    const float* __restrict__ bias0, const float* __restrict__ bias1,
    int gsel, int mhalf, int s)
{
    constexpr int KD = (MODE==0)? EE : HH;
    constexpr int NC = KD/32;
    bf16* sA = dynsm;
    bf16* sB = dynsm + 3*5120;
    const int tid = threadIdx.x;
    const int m0 = blockIdx.y*128, n0 = blockIdx.x*128;
    const int ss = s;
    const int dir = (m0 >= mhalf)? 1 : 0;
    const bf16* Bm;
    if (MODE==0) Bm = gsel? (dir? d_WbIB : d_WfIB) : d_WeIB;
    else Bm = dir? d_WbHB : d_WfHB;
    const float* bias = dir? bias1 : bias0;

    const int lrow = tid>>2, lc = (tid&3)*8;
    const bf16* arow;
    if (MODE==0){
        const int* tok = gsel? d_tokD : d_tokE;
        arow = d_embB + (long)tok[m0+lrow]*KD;
    } else {
        arow = d_HdecB + (long)ss*NDROW*HH + (long)(m0+lrow)*HH;
    }
    const int vrow = n0 + lrow;
    long browi;
    if (MODE==1){
        int gate = (vrow>>5)&3, hsub = vrow&31;
        browi = (long)gate*HH + (long)blockIdx.x*32 + hsub;
    } else {
        browi = (long)vrow;
    }
    const bf16* brow = Bm + browi*KD;

    const unsigned smA = sptr(sA), smB = sptr(sB);
    const unsigned ldoff = (unsigned)((lrow*40 + lc)*2);

    auto issue_chunk = [&](int kt, int st){
        int k0 = kt*32;
        cp16(smA + (unsigned)st*10240u + ldoff, arow + k0 + lc, 16);
        cp16(smB + (unsigned)st*10240u + ldoff, brow + k0 + lc, 16);
        asm volatile("cp.async.commit_group;" ::: "memory");
    };

    const int lane = tid&31, warp = tid>>5;
    const int wm = warp&3, wn = warp>>2;
    const int g = lane>>2, t4 = lane&3;
    const int rl = (lane&7) + ((lane>>3)&1)*8;
    const int ca = (lane>>4)*8;
    const int rb = (lane&7) + ((lane>>4)&1)*8;
    const int cb = ((lane>>3)&1)*8;

    float acc[2][4][4];
    #pragma unroll
    for (int i=0;i<2;i++)
        #pragma unroll
        for (int j=0;j<4;j++)
            #pragma unroll
            for (int e=0;e<4;e++) acc[i][j][e]=0.f;

    issue_chunk(0, 0);
    issue_chunk(1, 1);

    #pragma unroll 1
    for (int kt=0; kt<NC; kt++){
        asm volatile("cp.async.wait_group 1;" ::: "memory");
        __syncthreads();
        int nx = kt + 2;
        if (nx < NC) issue_chunk(nx, nx%3);
        else asm volatile("cp.async.commit_group;" ::: "memory");
        const bf16* Ab = sA + (kt%3)*5120;
        const bf16* Bb = sB + (kt%3)*5120;
        #pragma unroll
        for (int ks=0; ks<32; ks+=16){
            unsigned af[2][4], bfm[2][4];
            #pragma unroll
            for (int mf=0;mf<2;mf++)
                ldsm4(af[mf], sptr(Ab + (wm*32+mf*16+rl)*40 + ks + ca));
            #pragma unroll
            for (int p=0;p<2;p++)
                ldsm4(bfm[p], sptr(Bb + (wn*32+p*16+rb)*40 + ks + cb));
            #pragma unroll
            for (int mf=0;mf<2;mf++)
                #pragma unroll
                for (int nf=0;nf<4;nf++)
                    mma16(acc[mf][nf], af[mf], &bfm[nf>>1][(nf&1)*2]);
        }
    }

    if (MODE==0){
        float* Co = gsel? d_Pd : d_Xe;
        #pragma unroll
        for (int mf=0; mf<2; mf++)
            #pragma unroll
            for (int lohi=0; lohi<2; lohi++){
                int r = m0 + wm*32 + mf*16 + g + lohi*8;
                #pragma unroll
                for (int nf=0; nf<4; nf++){
                    int col = n0 + wn*32 + nf*8 + 2*t4;
                    float2 o;
                    o.x = acc[mf][nf][lohi*2+0] + bias[col];
                    o.y = acc[mf][nf][lohi*2+1] + bias[col+1];
                    *(float2*)&Co[(long)r*GG + col] = o;
                }
            }
    } else {
        __syncthreads();
        bf16* Gsm = dynsm;                    // [128][132]
        #pragma unroll
        for (int mf=0; mf<2; mf++)
            #pragma unroll
            for (int lohi=0; lohi<2; lohi++){
                int lr = wm*32 + mf*16 + g + lohi*8;
                int row = m0 + lr;
                int rr = row - dir*2048;
                int m = rr>>5, b2 = rr&31;
                int tp = (ss==0)? TT : min(m+ss-1, TT-1);
                const float* xr = d_Pd + ((long)(dir*PDT+tp)*BB + b2)*GG
                                + (long)wn*HH + (long)blockIdx.x*32;
                #pragma unroll
                for (int nf=0; nf<4; nf++){
                    int cs = nf*8 + 2*t4;
                    float gx = acc[mf][nf][lohi*2+0] + xr[cs];
                    float gy = acc[mf][nf][lohi*2+1] + xr[cs+1];
                    *(__nv_bfloat162*)&Gsm[lr*132 + wn*32 + cs] = __floats2bfloat162_rn(gx, gy);
                }
            }
        __syncthreads();
        #pragma unroll
        for (int k=0; k<8; k++){
            int p = tid*8 + k;
            int lr = p>>5, hsub = p&31;
            int row = m0 + lr;
            int h = blockIdx.x*32 + hsub;
            float gi = __bfloat162float(Gsm[lr*132 +  0 + hsub]);
            float gf = __bfloat162float(Gsm[lr*132 + 32 + hsub]);
            float g2 = __bfloat162float(Gsm[lr*132 + 64 + hsub]);
            float go = __bfloat162float(Gsm[lr*132 + 96 + hsub]);
            long ci = (long)row*HH + h;
            float cp = d_Cdec[(ss&1)*NDROW*HH + ci];
            float c = sigm(gf)*cp + sigm(gi)*tanhf(g2);
            float hn = sigm(go)*tanhf(c);
            d_Cdec[((ss+1)&1)*NDROW*HH + ci] = c;
            d_HdecB[(long)(ss+1)*NDROW*HH + ci] = __float2bfloat16_rn(hn);
            d_Hd8[(long)(ss+1)*NDROW*HH + ci] = to8(hn);
        }
    }
}

// ===================== fp8 vocab-logit GEMM + fused partial LSE =====================
// 512 threads, 16 warps, warp-tile 32x32, CTA 128x128, K=512 in 8 chunks of 64 (bytes).
// smem: 3 stages x (A 128x80B + B 128x80B) = 61440 bytes
#define L8_SMEM (3*2*128*80)
__global__ void __launch_bounds__(512,2) k_lse8(const float* __restrict__ fhb,
                                               const float* __restrict__ bhb){
    unsigned char* sm = (unsigned char*)dynsm;
    const int tid = threadIdx.x;
    const int m0 = blockIdx.y*128, n0 = blockIdx.x*128;
    const int ss = blockIdx.z;
    const int dir = (m0 >= 2048);
    const unsigned char* Bm = dir? d_hWb8 : d_hWf8;
    const float* bias = dir? bhb : fhb;

    const int lrow = tid>>2, lq = (tid&3)*16;
    const unsigned char* arow = d_Hd8 + (long)(ss+1)*NDROW*HH + (long)(m0+lrow)*HH;
    const int vrow = n0 + lrow;
    const bool bval = (vrow < VV);
    const unsigned char* brow = Bm + (long)(bval? vrow : 0)*HH;
    const int bok = bval? 16 : 0;

    const unsigned smb = sptr(sm);
    const unsigned ldoff = (unsigned)(lrow*80 + lq);

    auto issue_chunk = [&](int kt, int st){
        int k0 = kt*64;
        cp16(smb + (unsigned)st*20480u + ldoff, arow + k0 + lq, 16);
        cp16(smb + (unsigned)st*20480u + 10240u + ldoff, brow + k0 + lq, bok);
        asm volatile("cp.async.commit_group;" ::: "memory");
    };

    const int lane = tid&31, warp = tid>>5;
    const int wm = warp&3, wn = warp>>2;
    const int g = lane>>2, t4 = lane&3;
    const int rl = (lane&7) + ((lane>>3)&1)*8;
    const int ca = (lane>>4)*16;          // bytes
    const int rb = (lane&7) + ((lane>>4)&1)*8;
    const int cb = ((lane>>3)&1)*16;      // bytes

    float acc[2][4][4];
    #pragma unroll
    for (int i=0;i<2;i++)
        #pragma unroll
        for (int j=0;j<4;j++)
            #pragma unroll
            for (int e=0;e<4;e++) acc[i][j][e]=0.f;

    issue_chunk(0, 0);
    issue_chunk(1, 1);

    #pragma unroll 1
    for (int kt=0; kt<8; kt++){
        asm volatile("cp.async.wait_group 1;" ::: "memory");
        __syncthreads();
        int nx = kt + 2;
        if (nx < 8) issue_chunk(nx, nx%3);
        else asm volatile("cp.async.commit_group;" ::: "memory");
        const unsigned char* Ab = sm + (kt%3)*20480;
        const unsigned char* Bb = Ab + 10240;
        #pragma unroll
        for (int ks=0; ks<2; ks++){
            unsigned af[2][4], bfm[2][4];
            #pragma unroll
            for (int mf=0;mf<2;mf++)
                ldsm4(af[mf], sptr(Ab + (wm*32+mf*16+rl)*80 + ks*32 + ca));
            #pragma unroll
            for (int p=0;p<2;p++)
                ldsm4(bfm[p], sptr(Bb + (wn*32+p*16+rb)*80 + ks*32 + cb));
            #pragma unroll
            for (int mf=0;mf<2;mf++)
                #pragma unroll
                for (int nf=0;nf<4;nf++)
                    mma8f8(acc[mf][nf], af[mf], &bfm[nf>>1][(nf&1)*2]);
        }
    }

    int nb = (n0>>5) + wn;
    #pragma unroll
    for (int mf=0; mf<2; mf++)
        #pragma unroll
        for (int lohi=0; lohi<2; lohi++){
            int r = m0 + wm*32 + mf*16 + g + lohi*8;
            float z[8]; float mx = NEGF;
            #pragma unroll
            for (int nf=0; nf<4; nf++)
                #pragma unroll
                for (int e=0; e<2; e++){
                    int v = n0 + wn*32 + nf*8 + 2*t4 + e;
                    float zz = acc[mf][nf][lohi*2+e] + ((v<VV)? bias[v] : NEGF);
                    z[nf*2+e] = zz;
                    mx = fmaxf(mx, zz);
                }
            mx = fmaxf(mx, __shfl_xor_sync(0xffffffffu, mx, 1));
            mx = fmaxf(mx, __shfl_xor_sync(0xffffffffu, mx, 2));
            float smv = 0.f;
            #pragma unroll
            for (int j=0;j<8;j++) smv += __expf(z[j]-mx);
            smv += __shfl_xor_sync(0xffffffffu, smv, 1);
            smv += __shfl_xor_sync(0xffffffffu, smv, 2);
            if (t4 == 0 && nb < NP){
                int srow = ss*NDROW + r;
                d_part[((long)nb*SR + srow)*2    ] = mx;
                d_part[((long)nb*SR + srow)*2 + 1] = smv;
            }
        }
}

// ===================== tensor-core persistent encoder =====================
#define ESM_BYTES (64*520*2 + 64*520*2 + 64*66*4)
__global__ void __launch_bounds__(256) k_enc(const float* __restrict__ Whh){
    extern __shared__ char esm[];
    bf16* Ws  = (bf16*)esm;
    bf16* As  = Ws + 64*520;
    float* Gs = (float*)(As + 64*520);
    const int tid = threadIdx.x;
    const int h0 = blockIdx.x*16;

    {
        int c = tid>>2, t4w = tid&3;
        int gg = c&3, q = c>>2;
        const float* wr = Whh + (long)(gg*HH + h0 + q)*HH + t4w*128;
        bf16* dst = Ws + c*520 + t4w*128;
        #pragma unroll 4
        for (int j=0;j<128;j+=4){
            float4 v = *(const float4*)(wr+j);
            dst[j]   = __float2bfloat16_rn(v.x);
            dst[j+1] = __float2bfloat16_rn(v.y);
            dst[j+2] = __float2bfloat16_rn(v.z);
            dst[j+3] = __float2bfloat16_rn(v.w);
        }
    }
    __syncthreads();

    const int lane = tid&31, warp = tid>>5;
    const int wr4 = warp&3, wc = warp>>2;
    const int g = lane>>2, t4 = lane&3;
    const int rl = (lane&7) + ((lane>>3)&1)*8;
    const int ca = (lane>>4)*8;
    const int rb = (lane&7) + ((lane>>4)&1)*8;
    const int cb = ((lane>>3)&1)*8;
    const int srow = tid>>2, qd = tid&3;
    const int sdir = srow>>5, sb = srow&31;
    const int r = tid>>2, l4 = tid&3;
    const int dir = r>>5, b = r&31;

    const unsigned asbase = sptr(As) + (unsigned)((srow*520 + qd*128)*2);

    float cst[4] = {0.f,0.f,0.f,0.f};
    unsigned gen = 0;

    for (int t=0; t<TT; t++){
        {
            const bf16* src = d_HencB + ((long)(sdir*(TT+1)+t)*BB + sb)*HH + qd*128;
            #pragma unroll
            for (int i=0;i<16;i++) cp16(asbase + i*16u, src + i*8, 16);
            asm volatile("cp.async.commit_group;" ::: "memory");
            asm volatile("cp.async.wait_group 0;" ::: "memory");
        }
        __syncthreads();

        float acc[4][4];
        #pragma unroll
        for (int nf=0;nf<4;nf++)
            #pragma unroll
            for (int e=0;e<4;e++) acc[nf][e]=0.f;

        #pragma unroll 4
        for (int ks=0; ks<512; ks+=16){
            unsigned af[4], bfm[2][4];
            ldsm4(af, sptr(As + (16*wr4+rl)*520 + ks + ca));
            #pragma unroll
            for (int p=0;p<2;p++)
                ldsm4(bfm[p], sptr(Ws + (wc*32+p*16+rb)*520 + ks + cb));
            #pragma unroll
            for (int nf=0;nf<4;nf++)
                mma16(acc[nf], af, &bfm[nf>>1][(nf&1)*2]);
        }
        #pragma unroll
        for (int nf=0;nf<4;nf++){
            int col = wc*32 + nf*8 + 2*t4;
            Gs[(16*wr4+g)*66 + col]   = acc[nf][0];
            Gs[(16*wr4+g)*66 + col+1] = acc[nf][1];
            Gs[(16*wr4+g+8)*66 + col]   = acc[nf][2];
            Gs[(16*wr4+g+8)*66 + col+1] = acc[nf][3];
        }
        __syncthreads();
        {
            const float* xb = d_Xe + (long)(t*ROWS_E + r)*GG;
            #pragma unroll
            for (int j=0;j<4;j++){
                int q = l4 + 4*j; int h = h0 + q;
                float gi = Gs[r*66 + 4*q + 0] + xb[h];
                float gf = Gs[r*66 + 4*q + 1] + xb[HH+h];
                float g2 = Gs[r*66 + 4*q + 2] + xb[2*HH+h];
                float go = Gs[r*66 + 4*q + 3] + xb[3*HH+h];
                cst[j] = sigm(gf)*cst[j] + sigm(gi)*tanhf(g2);
                float hn = sigm(go)*tanhf(cst[j]);
                d_HencB[((long)(dir*(TT+1)+(t+1))*BB + b)*HH + h] = __float2bfloat16_rn(hn);
            }
        }
        __threadfence();
        __syncthreads();
        if (tid==0){
            unsigned a = atomicAdd(&g_cnt, 1u);
            if (a == gridDim.x-1){
                g_cnt = 0;
                __threadfence();
                atomicExch(&g_gen, gen+1u);
            } else {
                while (*((volatile unsigned*)&g_gen) != gen+1u) __nanosleep(32);
                __threadfence();
            }
        }
        __syncthreads();
        gen++;
    }
}

// ----- decoder init (reads bf16 encoder hidden) -----
__global__ void k_decinit(){
    int i = blockIdx.x*blockDim.x + threadIdx.x;
    int row = i>>9, h = i&511;
    int dir = row>>11, rr = row&2047, m = rr>>5, b = rr&31;
    bf16 v = d_HencB[((long)(dir*(TT+1)+(m+1))*BB+b)*HH + h];
    d_Cdec[i] = __bfloat162float(v);
    d_HdecB[i] = v;
}

// ----- gathered picks (bf16 inputs, fp32 accumulate) -----
__global__ void k_picks(const float* __restrict__ fhb, const float* __restrict__ bhb){
    int w = (blockIdx.x*blockDim.x + threadIdx.x) >> 5;
    int lane = threadIdx.x & 31;
    if (w >= 6*NDROW) return;
    int kind = w / NDROW;
    int row  = w % NDROW;
    int dir = row>>11, rr = row&2047, m = rr>>5, b = rr&31;
    const bf16* hW = dir ? d_hWbB : d_hWfB;
    const float* hb = dir ? bhb : fhb;
    int s, y;
    if (kind < 3){ s = kind;   y = d_tokD[dir*PDROWS + min(m+s, TT-1)*BB + b]; }
    else         { s = kind-2; y = 0; }
    const bf16* h = d_HdecB + (long)(s+1)*NDROW*HH + (long)row*HH;
    const bf16* wv = hW + (long)y*HH;
    float sum = 0.f;
    #pragma unroll 4
    for (int k=lane*2; k<HH; k+=64){
        __nv_bfloat162 a = *(const __nv_bfloat162*)(h+k);
        __nv_bfloat162 x = *(const __nv_bfloat162*)(wv+k);
        sum += __bfloat162float(a.x)*__bfloat162float(x.x)
             + __bfloat162float(a.y)*__bfloat162float(x.y);
    }
    #pragma unroll
    for (int off=16; off; off>>=1) sum += __shfl_xor_sync(0xffffffffu, sum, off);
    if (!lane){
        if (kind < 3) d_zc[s*NDROW + row] = sum + hb[y];
        else          d_zt[s*NDROW + row] = sum + hb[0];
    }
}

// ----- combine LSE partials -----
__global__ void k_lse2(){
    int i = blockIdx.x*blockDim.x + threadIdx.x;
    if (i >= SR) return;
    float mx = NEGF, sm = 0.f;
    for (int nb=0; nb<NP; nb++){
        float2 p = *(float2*)&d_part[((long)nb*SR + i)*2];
        if (p.x > mx){ sm = sm*__expf(mx-p.x) + p.y; mx = p.x; }
        else sm += p.y*__expf(p.x-mx);
    }
    d_lse[i] = mx + logf(sm);
}

// ----- segment scores -----
__global__ void k_res(){
    int i = blockIdx.x*blockDim.x + threadIdx.x;
    if (i >= NDROW) return;
    int dir = i>>11, rr = i&2047, m = rr>>5, b = rr&31;
    float cum = 0.f;
    #pragma unroll
    for (int l=0; l<WW; l++){
        cum += d_zc[l*NDROW+i] - d_lse[l*NDROW+i];
        float tg = d_zt[(l+1)*NDROW+i] - d_lse[(l+1)*NDROW+i];
        d_res[((dir*TT+m)*WW+l)*BB + b] = cum + tg;
    }
}

// ----- final DP -----
__global__ void k_final(float* __restrict__ out){
    int b = threadIdx.x;
    float w0 = 0.f, w1 = NEGF, w2 = NEGF;
    for (int e=0; e<TT; e++){
        float p[3];
        #pragma unroll
        for (int l=0; l<3; l++){
            int st = e - l;
            p[l] = (st >= 0) ? (d_res[((0*TT+st)*WW+l)*BB + b]
                              + d_res[((1*TT+(TT-1-e))*WW+l)*BB + b]) : NEGF;
        }
        float x0 = w0+p[0], x1 = w1+p[1], x2 = w2+p[2];
        float m = fmaxf(x0, fmaxf(x1, x2));
        float tot = m + logf(__expf(x0-m) + __expf(x1-m) + __expf(x2-m));
        w2 = w1; w1 = w0; w0 = tot;
    }
    float v = w0;
    #pragma unroll
    for (int off=16; off; off>>=1) v += __shfl_xor_sync(0xffffffffu, v, off);
    if (b == 0) out[0] = -v/(float)BB;
}

extern "C" void kernel_launch(void* const* d_in, const int* in_sizes, int n_in,
                              void* d_out, int out_size){
    const int*   sent = (const int*)  d_in[0];
    const float* emb  = (const float*)d_in[1];
    const float* eWih = (const float*)d_in[2];
    const float* eWhh = (const float*)d_in[3];
    const float* eB   = (const float*)d_in[4];
    const float* fWih = (const float*)d_in[5];
    const float* fWhh = (const float*)d_in[6];
    const float* fB   = (const float*)d_in[7];
    const float* fhW  = (const float*)d_in[8];
    const float* fhb  = (const float*)d_in[9];
    const float* bWih = (const float*)d_in[10];
    const float* bWhh = (const float*)d_in[11];
    const float* bB   = (const float*)d_in[12];
    const float* bhW  = (const float*)d_in[13];
    const float* bhb  = (const float*)d_in[14];
    float* out = (float*)d_out;

    cudaFuncSetAttribute(k_enc, cudaFuncAttributeMaxDynamicSharedMemorySize, ESM_BYTES);
    cudaFuncSetAttribute(k_bgemm<0>, cudaFuncAttributeMaxDynamicSharedMemorySize, BG_SMEM);
    cudaFuncSetAttribute(k_bgemm<1>, cudaFuncAttributeMaxDynamicSharedMemorySize, BG_SMEM);
    cudaFuncSetAttribute(k_lse8, cudaFuncAttributeMaxDynamicSharedMemorySize, L8_SMEM);

    k_init<<<128,256>>>(sent);
    {
        long nA = (long)VV*EE + 3L*GG*EE;
        long nB = 2L*GG*HH + 2L*VV*HH;
        long n8 = 2L*VV*HH;
        k_convA<<<(int)((nA/4+255)/256),256>>>(emb, eWih, fWih, bWih);
        k_convB<<<(int)((nB/4+255)/256),256>>>(fWhh, bWhh, fhW, bhW);
        k_conv8<<<(int)((n8/4+255)/256),256>>>(fhW, bhW);
    }
    k_bgemm<0><<<dim3(16,32,1),512,BG_SMEM>>>(eB, eB, 0, 1<<30, 0);
    k_bgemm<0><<<dim3(16,34,1),512,BG_SMEM>>>(fB, bB, 1, PDROWS, 0);
    k_enc<<<32,256,ESM_BYTES>>>(eWhh);
    k_decinit<<<8192,256>>>();
    for (int s=0; s<4; s++)
        k_bgemm<1><<<dim3(16,32,1),512,BG_SMEM>>>(0, 0, 0, 2048, s);
    k_picks<<<3072,256>>>(fhb, bhb);
    k_lse8<<<dim3(63,32,4),512,L8_SMEM>>>(fhb, bhb);
    k_lse2<<<64,256>>>();
    k_res<<<16,256>>>();
    k_final<<<1,32>>>(out);
}

// round 15
// speedup vs baseline: 1.0982x; 1.0982x over previous
#include <cuda_runtime.h>
#include <cuda_bf16.h>
#include <stdint.h>
#include <math.h>

#define BB 32
#define TT 64
#define VV 8000
#define EE 256
#define HH 512
#define GG 2048
#define WW 3
#define NEGF (-1e30f)
#define NDROW 4096
#define ROWS_E 64
#define PDT 68
#define PDROWS (PDT*BB)      // 2176
#define NP 250
#define SR (4*NDROW)

typedef __nv_bfloat16 bf16;

// ----- scratch -----
__device__ float d_Xe[TT*ROWS_E*GG];
__device__ float d_Pd[2*PDROWS*GG];
__device__ float d_Cdec[2*NDROW*HH];
__device__ int   d_tokE[TT*ROWS_E];
__device__ int   d_tokD[2*PDROWS];
__device__ float d_zc[3*NDROW];
__device__ float d_zt[4*NDROW];
__device__ float d_part[NP*SR*2];
__device__ float d_lse[4*NDROW];
__device__ float d_res[2*TT*WW*BB];
__device__ unsigned g_cnt;
__device__ unsigned g_gen;

// ----- bf16 mirrors -----
__device__ bf16 d_embB[VV*EE];
__device__ bf16 d_WeIB[GG*EE];
__device__ bf16 d_WfIB[GG*EE];
__device__ bf16 d_WbIB[GG*EE];
__device__ bf16 d_WfHB[GG*HH];
__device__ bf16 d_WbHB[GG*HH];
__device__ bf16 d_hWfB[VV*HH];
__device__ bf16 d_hWbB[VV*HH];
__device__ bf16 d_HencB[2*(TT+1)*BB*HH];
__device__ bf16 d_HdecB[5*NDROW*HH];

__device__ __forceinline__ float sigm(float x){ return 1.f/(1.f+__expf(-x)); }
__device__ __forceinline__ unsigned sptr(const void* p){
    return (unsigned)__cvta_generic_to_shared(p);
}
__device__ __forceinline__ void ldsm4(unsigned* r, unsigned a){
    asm volatile("ldmatrix.sync.aligned.m8n8.x4.shared.b16 {%0,%1,%2,%3}, [%4];\n"
        : "=r"(r[0]),"=r"(r[1]),"=r"(r[2]),"=r"(r[3]) : "r"(a));
}
__device__ __forceinline__ void mma16(float* c, const unsigned* a, const unsigned* b){
    asm volatile("mma.sync.aligned.m16n8k16.row.col.f32.bf16.bf16.f32 "
        "{%0,%1,%2,%3},{%4,%5,%6,%7},{%8,%9},{%0,%1,%2,%3};\n"
        : "+f"(c[0]),"+f"(c[1]),"+f"(c[2]),"+f"(c[3])
        : "r"(a[0]),"r"(a[1]),"r"(a[2]),"r"(a[3]),"r"(b[0]),"r"(b[1]));
}
__device__ __forceinline__ void cp16(unsigned dst, const void* src, int ssz){
    asm volatile("cp.async.cg.shared.global [%0], [%1], 16, %2;\n"
        :: "r"(dst), "l"(src), "r"(ssz));
}

// ----- fp32 -> bf16 conversion -----
__global__ void k_convA(const float* __restrict__ emb, const float* __restrict__ eWih,
                        const float* __restrict__ fWih, const float* __restrict__ bWih){
    const long n0 = (long)VV*EE, n1 = n0 + (long)GG*EE, n2 = n1 + (long)GG*EE, n3 = n2 + (long)GG*EE;
    long i = ((long)blockIdx.x*blockDim.x + threadIdx.x)*4;
    if (i >= n3) return;
    const float* src; bf16* dst; long off;
    if (i < n0){ src=emb; dst=d_embB; off=i; }
    else if (i < n1){ src=eWih; dst=d_WeIB; off=i-n0; }
    else if (i < n2){ src=fWih; dst=d_WfIB; off=i-n1; }
    else { src=bWih; dst=d_WbIB; off=i-n2; }
    float4 v = *(const float4*)(src+off);
    *(__nv_bfloat162*)(dst+off)   = __floats2bfloat162_rn(v.x, v.y);
    *(__nv_bfloat162*)(dst+off+2) = __floats2bfloat162_rn(v.z, v.w);
}
__global__ void k_convB(const float* __restrict__ fWhh, const float* __restrict__ bWhh,
                        const float* __restrict__ fhW, const float* __restrict__ bhW){
    const long n0 = (long)GG*HH, n1 = n0 + (long)GG*HH, n2 = n1 + (long)VV*HH, n3 = n2 + (long)VV*HH;
    long i = ((long)blockIdx.x*blockDim.x + threadIdx.x)*4;
    if (i >= n3) return;
    const float* src; bf16* dst; long off;
    if (i < n0){ src=fWhh; dst=d_WfHB; off=i; }
    else if (i < n1){ src=bWhh; dst=d_WbHB; off=i-n0; }
    else if (i < n2){ src=fhW; dst=d_hWfB; off=i-n1; }
    else { src=bhW; dst=d_hWbB; off=i-n2; }
    float4 v = *(const float4*)(src+off);
    *(__nv_bfloat162*)(dst+off)   = __floats2bfloat162_rn(v.x, v.y);
    *(__nv_bfloat162*)(dst+off+2) = __floats2bfloat162_rn(v.z, v.w);
}

// ----- init -----
__global__ void k_init(const int* __restrict__ sent){
    int i = blockIdx.x*blockDim.x + threadIdx.x;
    if (i == 0){ g_cnt = 0u; g_gen = 0u; }
    if (i < 2*BB*HH){
        int dir = i/(BB*HH); int rem = i%(BB*HH);
        d_HencB[(dir*(TT+1))*BB*HH + rem] = __float2bfloat16(0.f);
    }
    if (i < TT*ROWS_E){
        int t = i/ROWS_E, r = i%ROWS_E, dir = r/BB, b = r%BB;
        int tok = (t==0) ? 0 : (dir ? sent[b*TT + (TT-t)] : sent[b*TT + (t-1)]);
        d_tokE[i] = tok;
    }
    if (i < 2*PDROWS){
        int dir = i/PDROWS; int rem = i%PDROWS; int t = rem/BB, b = rem%BB;
        int tok = (t < TT) ? (dir ? sent[b*TT + (TT-1-t)] : sent[b*TT + t]) : 0;
        d_tokD[i] = tok;
    }
}

// ===================== bf16 mma.sync GEMM: 512 threads, 16 warps, warp-tile 32x32 =====================
// MODE 0: A=embB[tok], K=256, out Xe/Pd (+bias)
// MODE 1: A=HdecB[s],  K=512, gate-interleaved B rows; epilogue = fused LSTM cell
// MODE 2: A=HdecB[s+1],K=512, fused partial LSE
#define BG_SMEM (6*5120*2)     // 61440 bytes
extern __shared__ bf16 dynsm[];

template<int MODE>
__global__ void __launch_bounds__(512,2) k_bgemm(
    const float* __restrict__ bias0, const float* __restrict__ bias1,
    int gsel, int mhalf, int s)
{
    constexpr int KD = (MODE==0)? EE : HH;
    constexpr int NC = KD/32;
    bf16* sA = dynsm;
    bf16* sB = dynsm + 3*5120;
    const int tid = threadIdx.x;
    const int m0 = blockIdx.y*128, n0 = blockIdx.x*128;
    const int ss = (MODE==2)? (int)blockIdx.z : s;
    const int dir = (m0 >= mhalf)? 1 : 0;
    const bf16* Bm;
    if (MODE==0) Bm = gsel? (dir? d_WbIB : d_WfIB) : d_WeIB;
    else if (MODE==1) Bm = dir? d_WbHB : d_WfHB;
    else Bm = dir? d_hWbB : d_hWfB;
    const float* bias = dir? bias1 : bias0;

    const int lrow = tid>>2, lc = (tid&3)*8;
    const bf16* arow;
    if (MODE==0){
        const int* tok = gsel? d_tokD : d_tokE;
        arow = d_embB + (long)tok[m0+lrow]*KD;
    } else if (MODE==1){
        arow = d_HdecB + (long)ss*NDROW*HH + (long)(m0+lrow)*HH;
    } else {
        arow = d_HdecB + (long)(ss+1)*NDROW*HH + (long)(m0+lrow)*HH;
    }
    const int vrow = n0 + lrow;
    const bool bval = (MODE!=2) || (vrow < VV);
    long browi;
    if (MODE==1){
        int gate = (vrow>>5)&3, hsub = vrow&31;
        browi = (long)gate*HH + (long)blockIdx.x*32 + hsub;
    } else {
        browi = (long)(bval? vrow : 0);
    }
    const bf16* brow = Bm + browi*KD;
    const int bok = bval? 16 : 0;

    const unsigned smA = sptr(sA), smB = sptr(sB);
    const unsigned ldoff = (unsigned)((lrow*40 + lc)*2);

    auto issue_chunk = [&](int kt, int st){
        int k0 = kt*32;
        cp16(smA + (unsigned)st*10240u + ldoff, arow + k0 + lc, 16);
        cp16(smB + (unsigned)st*10240u + ldoff, brow + k0 + lc, bok);
        asm volatile("cp.async.commit_group;" ::: "memory");
    };

    const int lane = tid&31, warp = tid>>5;
    const int wm = warp&3, wn = warp>>2;
    const int g = lane>>2, t4 = lane&3;
    const int rl = (lane&7) + ((lane>>3)&1)*8;
    const int ca = (lane>>4)*8;
    const int rb = (lane&7) + ((lane>>4)&1)*8;
    const int cb = ((lane>>3)&1)*8;

    float acc[2][4][4];
    #pragma unroll
    for (int i=0;i<2;i++)
        #pragma unroll
        for (int j=0;j<4;j++)
            #pragma unroll
            for (int e=0;e<4;e++) acc[i][j][e]=0.f;

    issue_chunk(0, 0);
    issue_chunk(1, 1);

    #pragma unroll 1
    for (int kt=0; kt<NC; kt++){
        asm volatile("cp.async.wait_group 1;" ::: "memory");
        __syncthreads();
        int nx = kt + 2;
        if (nx < NC) issue_chunk(nx, nx%3);
        else asm volatile("cp.async.commit_group;" ::: "memory");
        const bf16* Ab = sA + (kt%3)*5120;
        const bf16* Bb = sB + (kt%3)*5120;
        #pragma unroll
        for (int ks=0; ks<32; ks+=16){
            unsigned af[2][4], bfm[2][4];
            #pragma unroll
            for (int mf=0;mf<2;mf++)
                ldsm4(af[mf], sptr(Ab + (wm*32+mf*16+rl)*40 + ks + ca));
            #pragma unroll
            for (int p=0;p<2;p++)
                ldsm4(bfm[p], sptr(Bb + (wn*32+p*16+rb)*40 + ks + cb));
            #pragma unroll
            for (int mf=0;mf<2;mf++)
                #pragma unroll
                for (int nf=0;nf<4;nf++)
                    mma16(acc[mf][nf], af[mf], &bfm[nf>>1][(nf&1)*2]);
        }
    }

    if (MODE==0){
        float* Co = gsel? d_Pd : d_Xe;
        #pragma unroll
        for (int mf=0; mf<2; mf++)
            #pragma unroll
            for (int lohi=0; lohi<2; lohi++){
                int r = m0 + wm*32 + mf*16 + g + lohi*8;
                #pragma unroll
                for (int nf=0; nf<4; nf++){
                    int col = n0 + wn*32 + nf*8 + 2*t4;
                    float2 o;
                    o.x = acc[mf][nf][lohi*2+0] + bias[col];
                    o.y = acc[mf][nf][lohi*2+1] + bias[col+1];
                    *(float2*)&Co[(long)r*GG + col] = o;
                }
            }
    } else if (MODE==1){
        __syncthreads();
        bf16* Gsm = dynsm;                    // [128][132]
        #pragma unroll
        for (int mf=0; mf<2; mf++)
            #pragma unroll
            for (int lohi=0; lohi<2; lohi++){
                int lr = wm*32 + mf*16 + g + lohi*8;
                int row = m0 + lr;
                int rr = row - dir*2048;
                int m = rr>>5, b2 = rr&31;
                int tp = (ss==0)? TT : min(m+ss-1, TT-1);
                const float* xr = d_Pd + ((long)(dir*PDT+tp)*BB + b2)*GG
                                + (long)wn*HH + (long)blockIdx.x*32;
                #pragma unroll
                for (int nf=0; nf<4; nf++){
                    int cs = nf*8 + 2*t4;
                    float gx = acc[mf][nf][lohi*2+0] + xr[cs];
                    float gy = acc[mf][nf][lohi*2+1] + xr[cs+1];
                    *(__nv_bfloat162*)&Gsm[lr*132 + wn*32 + cs] = __floats2bfloat162_rn(gx, gy);
                }
            }
        __syncthreads();
        #pragma unroll
        for (int k=0; k<8; k++){
            int p = tid*8 + k;
            int lr = p>>5, hsub = p&31;
            int row = m0 + lr;
            int h = blockIdx.x*32 + hsub;
            float gi = __bfloat162float(Gsm[lr*132 +  0 + hsub]);
            float gf = __bfloat162float(Gsm[lr*132 + 32 + hsub]);
            float g2 = __bfloat162float(Gsm[lr*132 + 64 + hsub]);
            float go = __bfloat162float(Gsm[lr*132 + 96 + hsub]);
            long ci = (long)row*HH + h;
            float cp = d_Cdec[(ss&1)*NDROW*HH + ci];
            float c = sigm(gf)*cp + sigm(gi)*tanhf(g2);
            float hn = sigm(go)*tanhf(c);
            d_Cdec[((ss+1)&1)*NDROW*HH + ci] = c;
            d_HdecB[(long)(ss+1)*NDROW*HH + ci] = __float2bfloat16_rn(hn);
        }
    } else {
        int nb = (n0>>5) + wn;
        #pragma unroll
        for (int mf=0; mf<2; mf++)
            #pragma unroll
            for (int lohi=0; lohi<2; lohi++){
                int r = m0 + wm*32 + mf*16 + g + lohi*8;
                float z[8]; float mx = NEGF;
                #pragma unroll
                for (int nf=0; nf<4; nf++)
                    #pragma unroll
                    for (int e=0; e<2; e++){
                        int v = n0 + wn*32 + nf*8 + 2*t4 + e;
                        float zz = acc[mf][nf][lohi*2+e] + ((v<VV)? bias[v] : NEGF);
                        z[nf*2+e] = zz;
                        mx = fmaxf(mx, zz);
                    }
                mx = fmaxf(mx, __shfl_xor_sync(0xffffffffu, mx, 1));
                mx = fmaxf(mx, __shfl_xor_sync(0xffffffffu, mx, 2));
                float sm = 0.f;
                #pragma unroll
                for (int j=0;j<8;j++) sm += __expf(z[j]-mx);
                sm += __shfl_xor_sync(0xffffffffu, sm, 1);
                sm += __shfl_xor_sync(0xffffffffu, sm, 2);
                if (t4 == 0 && nb < NP){
                    int srow = ss*NDROW + r;
                    d_part[((long)nb*SR + srow)*2    ] = mx;
                    d_part[((long)nb*SR + srow)*2 + 1] = sm;
                }
            }
    }
}

// ===================== persistent encoder: 64 blocks x 8 h-cols =====================
// smem: Ws[32][520] bf16 + As[64][520] bf16 + Gs[64][34] f32
#define ESM_BYTES (32*520*2 + 64*520*2 + 64*34*4)
__global__ void __launch_bounds__(256) k_enc(const float* __restrict__ Whh){
    extern __shared__ char esm[];
    bf16* Ws  = (bf16*)esm;                   // [32 gate-cols][520]
    bf16* As  = Ws + 32*520;                  // [64][520]
    float* Gs = (float*)(As + 64*520);        // [64][34]
    const int tid = threadIdx.x;
    const int h0 = blockIdx.x*8;

    {   // load + convert Whh slice: col c=4q+g <- Whh row g*512+h0+q, q=0..7
        int c = tid>>3, t8 = tid&7;
        int gg = c&3, q = c>>2;
        const float* wr = Whh + (long)(gg*HH + h0 + q)*HH + t8*64;
        bf16* dst = Ws + c*520 + t8*64;
        #pragma unroll 4
        for (int j=0;j<64;j+=4){
            float4 v = *(const float4*)(wr+j);
            dst[j]   = __float2bfloat16_rn(v.x);
            dst[j+1] = __float2bfloat16_rn(v.y);
            dst[j+2] = __float2bfloat16_rn(v.z);
            dst[j+3] = __float2bfloat16_rn(v.w);
        }
    }
    __syncthreads();

    const int lane = tid&31, warp = tid>>5;
    const int wr4 = warp&3, wc = warp>>2;     // 4 row-groups x 2 col-groups(16)
    const int g = lane>>2, t4 = lane&3;
    const int rl = (lane&7) + ((lane>>3)&1)*8;
    const int ca = (lane>>4)*8;
    const int rb = (lane&7) + ((lane>>4)&1)*8;
    const int cb = ((lane>>3)&1)*8;
    const int srow = tid>>2, qd = tid&3;
    const int sdir = srow>>5, sb = srow&31;

    const unsigned asbase = sptr(As) + (unsigned)((srow*520 + qd*128)*2);

    float cst[2] = {0.f,0.f};
    unsigned gen = 0;

    for (int t=0; t<TT; t++){
        {
            const bf16* src = d_HencB + ((long)(sdir*(TT+1)+t)*BB + sb)*HH + qd*128;
            #pragma unroll
            for (int i=0;i<16;i++) cp16(asbase + i*16u, src + i*8, 16);
            asm volatile("cp.async.commit_group;" ::: "memory");
            asm volatile("cp.async.wait_group 0;" ::: "memory");
        }
        __syncthreads();

        float acc[2][4];
        #pragma unroll
        for (int nf=0;nf<2;nf++)
            #pragma unroll
            for (int e=0;e<4;e++) acc[nf][e]=0.f;

        #pragma unroll 4
        for (int ks=0; ks<512; ks+=16){
            unsigned af[4], bfm[4];
            ldsm4(af, sptr(As + (16*wr4+rl)*520 + ks + ca));
            ldsm4(bfm, sptr(Ws + (wc*16+rb)*520 + ks + cb));
            mma16(acc[0], af, &bfm[0]);
            mma16(acc[1], af, &bfm[2]);
        }
        #pragma unroll
        for (int nf=0;nf<2;nf++){
            int col = wc*16 + nf*8 + 2*t4;
            Gs[(16*wr4+g)*34 + col]   = acc[nf][0];
            Gs[(16*wr4+g)*34 + col+1] = acc[nf][1];
            Gs[(16*wr4+g+8)*34 + col]   = acc[nf][2];
            Gs[(16*wr4+g+8)*34 + col+1] = acc[nf][3];
        }
        __syncthreads();
        // cell update: thread handles p = tid*2+k -> (row, q)
        #pragma unroll
        for (int k=0;k<2;k++){
            int p = tid*2 + k;
            int row = p>>3, q = p&7;
            int h = h0 + q;
            int dir = row>>5, b = row&31;
            const float* xb = d_Xe + (long)(t*ROWS_E + row)*GG;
            float gi = Gs[row*34 + 4*q + 0] + xb[h];
            float gf = Gs[row*34 + 4*q + 1] + xb[HH+h];
            float g2 = Gs[row*34 + 4*q + 2] + xb[2*HH+h];
            float go = Gs[row*34 + 4*q + 3] + xb[3*HH+h];
            cst[k] = sigm(gf)*cst[k] + sigm(gi)*tanhf(g2);
            float hn = sigm(go)*tanhf(cst[k]);
            d_HencB[((long)(dir*(TT+1)+(t+1))*BB + b)*HH + h] = __float2bfloat16_rn(hn);
        }
        __threadfence();
        __syncthreads();
        if (tid==0){
            unsigned a = atomicAdd(&g_cnt, 1u);
            if (a == gridDim.x-1){
                g_cnt = 0;
                __threadfence();
                atomicExch(&g_gen, gen+1u);
            } else {
                while (*((volatile unsigned*)&g_gen) != gen+1u) __nanosleep(32);
                __threadfence();
            }
        }
        __syncthreads();
        gen++;
    }
}

// ----- decoder init (reads bf16 encoder hidden) -----
__global__ void k_decinit(){
    int i = blockIdx.x*blockDim.x + threadIdx.x;
    int row = i>>9, h = i&511;
    int dir = row>>11, rr = row&2047, m = rr>>5, b = rr&31;
    bf16 v = d_HencB[((long)(dir*(TT+1)+(m+1))*BB+b)*HH + h];
    d_Cdec[i] = __bfloat162float(v);
    d_HdecB[i] = v;
}

// ----- gathered picks -----
__global__ void k_picks(const float* __restrict__ fhb, const float* __restrict__ bhb){
    int w = (blockIdx.x*blockDim.x + threadIdx.x) >> 5;
    int lane = threadIdx.x & 31;
    if (w >= 6*NDROW) return;
    int kind = w / NDROW;
    int row  = w % NDROW;
    int dir = row>>11, rr = row&2047, m = rr>>5, b = rr&31;
    const bf16* hW = dir ? d_hWbB : d_hWfB;
    const float* hb = dir ? bhb : fhb;
    int s, y;
    if (kind < 3){ s = kind;   y = d_tokD[dir*PDROWS + min(m+s, TT-1)*BB + b]; }
    else         { s = kind-2; y = 0; }
    const bf16* h = d_HdecB + (long)(s+1)*NDROW*HH + (long)row*HH;
    const bf16* wv = hW + (long)y*HH;
    float sum = 0.f;
    #pragma unroll 4
    for (int k=lane*2; k<HH; k+=64){
        __nv_bfloat162 a = *(const __nv_bfloat162*)(h+k);
        __nv_bfloat162 x = *(const __nv_bfloat162*)(wv+k);
        sum += __bfloat162float(a.x)*__bfloat162float(x.x)
             + __bfloat162float(a.y)*__bfloat162float(x.y);
    }
    #pragma unroll
    for (int off=16; off; off>>=1) sum += __shfl_xor_sync(0xffffffffu, sum, off);
    if (!lane){
        if (kind < 3) d_zc[s*NDROW + row] = sum + hb[y];
        else          d_zt[s*NDROW + row] = sum + hb[0];
    }
}

// ----- combine LSE partials -----
__global__ void k_lse2(){
    int i = blockIdx.x*blockDim.x + threadIdx.x;
    if (i >= SR) return;
    float mx = NEGF, sm = 0.f;
    for (int nb=0; nb<NP; nb++){
        float2 p = *(float2*)&d_part[((long)nb*SR + i)*2];
        if (p.x > mx){ sm = sm*__expf(mx-p.x) + p.y; mx = p.x; }
        else sm += p.y*__expf(p.x-mx);
    }
    d_lse[i] = mx + logf(sm);
}

// ----- segment scores -----
__global__ void k_res(){
    int i = blockIdx.x*blockDim.x + threadIdx.x;
    if (i >= NDROW) return;
    int dir = i>>11, rr = i&2047, m = rr>>5, b = rr&31;
    float cum = 0.f;
    #pragma unroll
    for (int l=0; l<WW; l++){
        cum += d_zc[l*NDROW+i] - d_lse[l*NDROW+i];
        float tg = d_zt[(l+1)*NDROW+i] - d_lse[(l+1)*NDROW+i];
        d_res[((dir*TT+m)*WW+l)*BB + b] = cum + tg;
    }
}

// ----- final DP -----
__global__ void k_final(float* __restrict__ out){
    int b = threadIdx.x;
    float w0 = 0.f, w1 = NEGF, w2 = NEGF;
    for (int e=0; e<TT; e++){
        float p[3];
        #pragma unroll
        for (int l=0; l<3; l++){
            int st = e - l;
            p[l] = (st >= 0) ? (d_res[((0*TT+st)*WW+l)*BB + b]
                              + d_res[((1*TT+(TT-1-e))*WW+l)*BB + b]) : NEGF;
        }
        float x0 = w0+p[0], x1 = w1+p[1], x2 = w2+p[2];
        float m = fmaxf(x0, fmaxf(x1, x2));
        float tot = m + logf(__expf(x0-m) + __expf(x1-m) + __expf(x2-m));
        w2 = w1; w1 = w0; w0 = tot;
    }
    float v = w0;
    #pragma unroll
    for (int off=16; off; off>>=1) v += __shfl_xor_sync(0xffffffffu, v, off);
    if (b == 0) out[0] = -v/(float)BB;
}

extern "C" void kernel_launch(void* const* d_in, const int* in_sizes, int n_in,
                              void* d_out, int out_size){
    const int*   sent = (const int*)  d_in[0];
    const float* emb  = (const float*)d_in[1];
    const float* eWih = (const float*)d_in[2];
    const float* eWhh = (const float*)d_in[3];
    const float* eB   = (const float*)d_in[4];
    const float* fWih = (const float*)d_in[5];
    const float* fWhh = (const float*)d_in[6];
    const float* fB   = (const float*)d_in[7];
    const float* fhW  = (const float*)d_in[8];
    const float* fhb  = (const float*)d_in[9];
    const float* bWih = (const float*)d_in[10];
    const float* bWhh = (const float*)d_in[11];
    const float* bB   = (const float*)d_in[12];
    const float* bhW  = (const float*)d_in[13];
    const float* bhb  = (const float*)d_in[14];
    float* out = (float*)d_out;

    cudaFuncSetAttribute(k_enc, cudaFuncAttributeMaxDynamicSharedMemorySize, ESM_BYTES);
    cudaFuncSetAttribute(k_bgemm<0>, cudaFuncAttributeMaxDynamicSharedMemorySize, BG_SMEM);
    cudaFuncSetAttribute(k_bgemm<1>, cudaFuncAttributeMaxDynamicSharedMemorySize, BG_SMEM);
    cudaFuncSetAttribute(k_bgemm<2>, cudaFuncAttributeMaxDynamicSharedMemorySize, BG_SMEM);

    k_init<<<128,256>>>(sent);
    {
        long nA = (long)VV*EE + 3L*GG*EE;
        long nB = 2L*GG*HH + 2L*VV*HH;
        k_convA<<<(int)((nA/4+255)/256),256>>>(emb, eWih, fWih, bWih);
        k_convB<<<(int)((nB/4+255)/256),256>>>(fWhh, bWhh, fhW, bhW);
    }
    k_bgemm<0><<<dim3(16,32,1),512,BG_SMEM>>>(eB, eB, 0, 1<<30, 0);
    k_bgemm<0><<<dim3(16,34,1),512,BG_SMEM>>>(fB, bB, 1, PDROWS, 0);
    k_enc<<<64,256,ESM_BYTES>>>(eWhh);
    k_decinit<<<8192,256>>>();
    for (int s=0; s<4; s++)
        k_bgemm<1><<<dim3(16,32,1),512,BG_SMEM>>>(0, 0, 0, 2048, s);
    k_picks<<<3072,256>>>(fhb, bhb);
    k_bgemm<2><<<dim3(63,32,4),512,BG_SMEM>>>(fhb, bhb, 0, 2048, 0);
    k_lse2<<<64,256>>>();
    k_res<<<16,256>>>();
    k_final<<<1,32>>>(out);
}

// round 16
// speedup vs baseline: 1.1511x; 1.0482x over previous
#include <cuda_runtime.h>
#include <cuda_bf16.h>
#include <stdint.h>
#include <math.h>

#define BB 32
#define TT 64
#define VV 8000
#define EE 256
#define HH 512
#define GG 2048
#define WW 3
#define NEGF (-1e30f)
#define NDROW 4096
#define ROWS_E 64
#define PDT 68
#define PDROWS (PDT*BB)      // 2176
#define NP2 63               // combined vocab partials (128-wide)
#define SR (4*NDROW)

typedef __nv_bfloat16 bf16;

// ----- scratch -----
__device__ float d_Xe[TT*ROWS_E*GG];
__device__ float d_Pd[2*PDROWS*GG];
__device__ float d_Cdec[2*NDROW*HH];
__device__ int   d_tokE[TT*ROWS_E];
__device__ int   d_tokD[2*PDROWS];
__device__ float d_zc[3*NDROW];
__device__ float d_zt[4*NDROW];
__device__ float d_part[NP2*SR*2];
__device__ float d_lse[4*NDROW];
__device__ float d_res[2*TT*WW*BB];
__device__ unsigned g_cnt;
__device__ unsigned g_gen;

// ----- bf16 mirrors -----
__device__ bf16 d_embB[VV*EE];
__device__ bf16 d_WeIB[GG*EE];
__device__ bf16 d_WfIB[GG*EE];
__device__ bf16 d_WbIB[GG*EE];
__device__ bf16 d_WfHB[GG*HH];
__device__ bf16 d_WbHB[GG*HH];
__device__ bf16 d_hWfB[VV*HH];
__device__ bf16 d_hWbB[VV*HH];
__device__ bf16 d_HencB[2*(TT+1)*BB*HH];
__device__ bf16 d_HdecB[5*NDROW*HH];

__device__ __forceinline__ float sigm(float x){ return 1.f/(1.f+__expf(-x)); }
__device__ __forceinline__ unsigned sptr(const void* p){
    return (unsigned)__cvta_generic_to_shared(p);
}
__device__ __forceinline__ void ldsm4(unsigned* r, unsigned a){
    asm volatile("ldmatrix.sync.aligned.m8n8.x4.shared.b16 {%0,%1,%2,%3}, [%4];\n"
        : "=r"(r[0]),"=r"(r[1]),"=r"(r[2]),"=r"(r[3]) : "r"(a));
}
__device__ __forceinline__ void mma16(float* c, const unsigned* a, const unsigned* b){
    asm volatile("mma.sync.aligned.m16n8k16.row.col.f32.bf16.bf16.f32 "
        "{%0,%1,%2,%3},{%4,%5,%6,%7},{%8,%9},{%0,%1,%2,%3};\n"
        : "+f"(c[0]),"+f"(c[1]),"+f"(c[2]),"+f"(c[3])
        : "r"(a[0]),"r"(a[1]),"r"(a[2]),"r"(a[3]),"r"(b[0]),"r"(b[1]));
}
__device__ __forceinline__ void cp16(unsigned dst, const void* src, int ssz){
    asm volatile("cp.async.cg.shared.global [%0], [%1], 16, %2;\n"
        :: "r"(dst), "l"(src), "r"(ssz));
}

// ----- fp32 -> bf16 conversion -----
__global__ void k_convA(const float* __restrict__ emb, const float* __restrict__ eWih,
                        const float* __restrict__ fWih, const float* __restrict__ bWih){
    const long n0 = (long)VV*EE, n1 = n0 + (long)GG*EE, n2 = n1 + (long)GG*EE, n3 = n2 + (long)GG*EE;
    long i = ((long)blockIdx.x*blockDim.x + threadIdx.x)*4;
    if (i >= n3) return;
    const float* src; bf16* dst; long off;
    if (i < n0){ src=emb; dst=d_embB; off=i; }
    else if (i < n1){ src=eWih; dst=d_WeIB; off=i-n0; }
    else if (i < n2){ src=fWih; dst=d_WfIB; off=i-n1; }
    else { src=bWih; dst=d_WbIB; off=i-n2; }
    float4 v = *(const float4*)(src+off);
    *(__nv_bfloat162*)(dst+off)   = __floats2bfloat162_rn(v.x, v.y);
    *(__nv_bfloat162*)(dst+off+2) = __floats2bfloat162_rn(v.z, v.w);
}
__global__ void k_convB(const float* __restrict__ fWhh, const float* __restrict__ bWhh,
                        const float* __restrict__ fhW, const float* __restrict__ bhW){
    const long n0 = (long)GG*HH, n1 = n0 + (long)GG*HH, n2 = n1 + (long)VV*HH, n3 = n2 + (long)VV*HH;
    long i = ((long)blockIdx.x*blockDim.x + threadIdx.x)*4;
    if (i >= n3) return;
    const float* src; bf16* dst; long off;
    if (i < n0){ src=fWhh; dst=d_WfHB; off=i; }
    else if (i < n1){ src=bWhh; dst=d_WbHB; off=i-n0; }
    else if (i < n2){ src=fhW; dst=d_hWfB; off=i-n1; }
    else { src=bhW; dst=d_hWbB; off=i-n2; }
    float4 v = *(const float4*)(src+off);
    *(__nv_bfloat162*)(dst+off)   = __floats2bfloat162_rn(v.x, v.y);
    *(__nv_bfloat162*)(dst+off+2) = __floats2bfloat162_rn(v.z, v.w);
}

// ----- init -----
__global__ void k_init(const int* __restrict__ sent){
    int i = blockIdx.x*blockDim.x + threadIdx.x;
    if (i == 0){ g_cnt = 0u; g_gen = 0u; }
    if (i < 2*BB*HH){
        int dir = i/(BB*HH); int rem = i%(BB*HH);
        d_HencB[(dir*(TT+1))*BB*HH + rem] = __float2bfloat16(0.f);
    }
    if (i < TT*ROWS_E){
        int t = i/ROWS_E, r = i%ROWS_E, dir = r/BB, b = r%BB;
        int tok = (t==0) ? 0 : (dir ? sent[b*TT + (TT-t)] : sent[b*TT + (t-1)]);
        d_tokE[i] = tok;
    }
    if (i < 2*PDROWS){
        int dir = i/PDROWS; int rem = i%PDROWS; int t = rem/BB, b = rem%BB;
        int tok = (t < TT) ? (dir ? sent[b*TT + (TT-1-t)] : sent[b*TT + t]) : 0;
        d_tokD[i] = tok;
    }
}

// ===================== bf16 mma.sync GEMM: 512 threads, 16 warps, warp-tile 32x32 =====================
// MODE 0: A=embB[tok], K=256, out Xe/Pd (+bias)
// MODE 1: A=HdecB[s],  K=512, gate-interleaved B rows; epilogue = fused LSTM cell
// MODE 2: A=HdecB[s+1],K=512, fused partial LSE with in-CTA wn-combine
#define BG_SMEM (6*5120*2)     // 61440 bytes
extern __shared__ bf16 dynsm[];

template<int MODE>
__global__ void __launch_bounds__(512,2) k_bgemm(
    const float* __restrict__ bias0, const float* __restrict__ bias1,
    int gsel, int mhalf, int s)
{
    constexpr int KD = (MODE==0)? EE : HH;
    constexpr int NC = KD/32;
    bf16* sA = dynsm;
    bf16* sB = dynsm + 3*5120;
    const int tid = threadIdx.x;
    const int m0 = blockIdx.y*128, n0 = blockIdx.x*128;
    const int ss = (MODE==2)? (int)blockIdx.z : s;
    const int dir = (m0 >= mhalf)? 1 : 0;
    const bf16* Bm;
    if (MODE==0) Bm = gsel? (dir? d_WbIB : d_WfIB) : d_WeIB;
    else if (MODE==1) Bm = dir? d_WbHB : d_WfHB;
    else Bm = dir? d_hWbB : d_hWfB;
    const float* bias = dir? bias1 : bias0;

    const int lrow = tid>>2, lc = (tid&3)*8;
    const bf16* arow;
    if (MODE==0){
        const int* tok = gsel? d_tokD : d_tokE;
        arow = d_embB + (long)tok[m0+lrow]*KD;
    } else if (MODE==1){
        arow = d_HdecB + (long)ss*NDROW*HH + (long)(m0+lrow)*HH;
    } else {
        arow = d_HdecB + (long)(ss+1)*NDROW*HH + (long)(m0+lrow)*HH;
    }
    const int vrow = n0 + lrow;
    const bool bval = (MODE!=2) || (vrow < VV);
    long browi;
    if (MODE==1){
        int gate = (vrow>>5)&3, hsub = vrow&31;
        browi = (long)gate*HH + (long)blockIdx.x*32 + hsub;
    } else {
        browi = (long)(bval? vrow : 0);
    }
    const bf16* brow = Bm + browi*KD;
    const int bok = bval? 16 : 0;

    const unsigned smA = sptr(sA), smB = sptr(sB);
    const unsigned ldoff = (unsigned)((lrow*40 + lc)*2);

    auto issue_chunk = [&](int kt, int st){
        int k0 = kt*32;
        cp16(smA + (unsigned)st*10240u + ldoff, arow + k0 + lc, 16);
        cp16(smB + (unsigned)st*10240u + ldoff, brow + k0 + lc, bok);
        asm volatile("cp.async.commit_group;" ::: "memory");
    };

    const int lane = tid&31, warp = tid>>5;
    const int wm = warp&3, wn = warp>>2;
    const int g = lane>>2, t4 = lane&3;
    const int rl = (lane&7) + ((lane>>3)&1)*8;
    const int ca = (lane>>4)*8;
    const int rb = (lane&7) + ((lane>>4)&1)*8;
    const int cb = ((lane>>3)&1)*8;

    float acc[2][4][4];
    #pragma unroll
    for (int i=0;i<2;i++)
        #pragma unroll
        for (int j=0;j<4;j++)
            #pragma unroll
            for (int e=0;e<4;e++) acc[i][j][e]=0.f;

    issue_chunk(0, 0);
    issue_chunk(1, 1);

    #pragma unroll 1
    for (int kt=0; kt<NC; kt++){
        asm volatile("cp.async.wait_group 1;" ::: "memory");
        __syncthreads();
        int nx = kt + 2;
        if (nx < NC) issue_chunk(nx, nx%3);
        else asm volatile("cp.async.commit_group;" ::: "memory");
        const bf16* Ab = sA + (kt%3)*5120;
        const bf16* Bb = sB + (kt%3)*5120;
        #pragma unroll
        for (int ks=0; ks<32; ks+=16){
            unsigned af[2][4], bfm[2][4];
            #pragma unroll
            for (int mf=0;mf<2;mf++)
                ldsm4(af[mf], sptr(Ab + (wm*32+mf*16+rl)*40 + ks + ca));
            #pragma unroll
            for (int p=0;p<2;p++)
                ldsm4(bfm[p], sptr(Bb + (wn*32+p*16+rb)*40 + ks + cb));
            #pragma unroll
            for (int mf=0;mf<2;mf++)
                #pragma unroll
                for (int nf=0;nf<4;nf++)
                    mma16(acc[mf][nf], af[mf], &bfm[nf>>1][(nf&1)*2]);
        }
    }

    if (MODE==0){
        float* Co = gsel? d_Pd : d_Xe;
        #pragma unroll
        for (int mf=0; mf<2; mf++)
            #pragma unroll
            for (int lohi=0; lohi<2; lohi++){
                int r = m0 + wm*32 + mf*16 + g + lohi*8;
                #pragma unroll
                for (int nf=0; nf<4; nf++){
                    int col = n0 + wn*32 + nf*8 + 2*t4;
                    float2 o;
                    o.x = acc[mf][nf][lohi*2+0] + bias[col];
                    o.y = acc[mf][nf][lohi*2+1] + bias[col+1];
                    *(float2*)&Co[(long)r*GG + col] = o;
                }
            }
    } else if (MODE==1){
        __syncthreads();
        bf16* Gsm = dynsm;                    // [128][132]
        #pragma unroll
        for (int mf=0; mf<2; mf++)
            #pragma unroll
            for (int lohi=0; lohi<2; lohi++){
                int lr = wm*32 + mf*16 + g + lohi*8;
                int row = m0 + lr;
                int rr = row - dir*2048;
                int m = rr>>5, b2 = rr&31;
                int tp = (ss==0)? TT : min(m+ss-1, TT-1);
                const float* xr = d_Pd + ((long)(dir*PDT+tp)*BB + b2)*GG
                                + (long)wn*HH + (long)blockIdx.x*32;
                #pragma unroll
                for (int nf=0; nf<4; nf++){
                    int cs = nf*8 + 2*t4;
                    float gx = acc[mf][nf][lohi*2+0] + xr[cs];
                    float gy = acc[mf][nf][lohi*2+1] + xr[cs+1];
                    *(__nv_bfloat162*)&Gsm[lr*132 + wn*32 + cs] = __floats2bfloat162_rn(gx, gy);
                }
            }
        __syncthreads();
        #pragma unroll
        for (int k=0; k<8; k++){
            int p = tid*8 + k;
            int lr = p>>5, hsub = p&31;
            int row = m0 + lr;
            int h = blockIdx.x*32 + hsub;
            float gi = __bfloat162float(Gsm[lr*132 +  0 + hsub]);
            float gf = __bfloat162float(Gsm[lr*132 + 32 + hsub]);
            float g2 = __bfloat162float(Gsm[lr*132 + 64 + hsub]);
            float go = __bfloat162float(Gsm[lr*132 + 96 + hsub]);
            long ci = (long)row*HH + h;
            float cp = d_Cdec[(ss&1)*NDROW*HH + ci];
            float c = sigm(gf)*cp + sigm(gi)*tanhf(g2);
            float hn = sigm(go)*tanhf(c);
            d_Cdec[((ss+1)&1)*NDROW*HH + ci] = c;
            d_HdecB[(long)(ss+1)*NDROW*HH + ci] = __float2bfloat16_rn(hn);
        }
    } else {
        // per-strip (32-wide) LSE, then in-CTA combine across the 4 wn strips
        __syncthreads();                      // smem pipeline no longer needed
        float2* buf = (float2*)dynsm;         // [128][4]
        #pragma unroll
        for (int mf=0; mf<2; mf++)
            #pragma unroll
            for (int lohi=0; lohi<2; lohi++){
                int lr = wm*32 + mf*16 + g + lohi*8;
                float z[8]; float mx = NEGF;
                #pragma unroll
                for (int nf=0; nf<4; nf++)
                    #pragma unroll
                    for (int e=0; e<2; e++){
                        int v = n0 + wn*32 + nf*8 + 2*t4 + e;
                        float zz = acc[mf][nf][lohi*2+e] + ((v<VV)? bias[v] : NEGF);
                        z[nf*2+e] = zz;
                        mx = fmaxf(mx, zz);
                    }
                mx = fmaxf(mx, __shfl_xor_sync(0xffffffffu, mx, 1));
                mx = fmaxf(mx, __shfl_xor_sync(0xffffffffu, mx, 2));
                float sm = 0.f;
                #pragma unroll
                for (int j=0;j<8;j++) sm += __expf(z[j]-mx);
                sm += __shfl_xor_sync(0xffffffffu, sm, 1);
                sm += __shfl_xor_sync(0xffffffffu, sm, 2);
                if (t4 == 0){
                    bool valid = (n0 + wn*32) < VV;
                    buf[lr*4 + wn] = valid? make_float2(mx, sm) : make_float2(NEGF, 0.f);
                }
            }
        __syncthreads();
        if (tid < 128){
            int lr = tid;
            float mx = NEGF, sv = 0.f;
            #pragma unroll
            for (int j=0;j<4;j++){
                float2 p = buf[lr*4+j];
                if (p.x > mx){ sv = sv*__expf(mx-p.x) + p.y; mx = p.x; }
                else sv += p.y*__expf(p.x-mx);
            }
            long srow = (long)ss*NDROW + m0 + lr;
            d_part[((long)blockIdx.x*SR + srow)*2    ] = mx;
            d_part[((long)blockIdx.x*SR + srow)*2 + 1] = sv;
        }
    }
}

// ===================== persistent encoder: 64 blocks x 8 h-cols =====================
// smem: Ws[32][520] bf16 + As[64][520] bf16 + Gs[64][34] f32
#define ESM_BYTES (32*520*2 + 64*520*2 + 64*34*4)
__global__ void __launch_bounds__(256) k_enc(const float* __restrict__ Whh){
    extern __shared__ char esm[];
    bf16* Ws  = (bf16*)esm;
    bf16* As  = Ws + 32*520;
    float* Gs = (float*)(As + 64*520);
    const int tid = threadIdx.x;
    const int h0 = blockIdx.x*8;

    {
        int c = tid>>3, t8 = tid&7;
        int gg = c&3, q = c>>2;
        const float* wr = Whh + (long)(gg*HH + h0 + q)*HH + t8*64;
        bf16* dst = Ws + c*520 + t8*64;
        #pragma unroll 4
        for (int j=0;j<64;j+=4){
            float4 v = *(const float4*)(wr+j);
            dst[j]   = __float2bfloat16_rn(v.x);
            dst[j+1] = __float2bfloat16_rn(v.y);
            dst[j+2] = __float2bfloat16_rn(v.z);
            dst[j+3] = __float2bfloat16_rn(v.w);
        }
    }
    __syncthreads();

    const int lane = tid&31, warp = tid>>5;
    const int wr4 = warp&3, wc = warp>>2;
    const int g = lane>>2, t4 = lane&3;
    const int rl = (lane&7) + ((lane>>3)&1)*8;
    const int ca = (lane>>4)*8;
    const int rb = (lane&7) + ((lane>>4)&1)*8;
    const int cb = ((lane>>3)&1)*8;
    const int srow = tid>>2, qd = tid&3;
    const int sdir = srow>>5, sb = srow&31;

    const unsigned asbase = sptr(As) + (unsigned)((srow*520 + qd*128)*2);

    float cst[2] = {0.f,0.f};
    unsigned gen = 0;

    for (int t=0; t<TT; t++){
        {
            const bf16* src = d_HencB + ((long)(sdir*(TT+1)+t)*BB + sb)*HH + qd*128;
            #pragma unroll
            for (int i=0;i<16;i++) cp16(asbase + i*16u, src + i*8, 16);
            asm volatile("cp.async.commit_group;" ::: "memory");
            asm volatile("cp.async.wait_group 0;" ::: "memory");
        }
        __syncthreads();

        float acc[2][4];
        #pragma unroll
        for (int nf=0;nf<2;nf++)
            #pragma unroll
            for (int e=0;e<4;e++) acc[nf][e]=0.f;

        #pragma unroll 4
        for (int ks=0; ks<512; ks+=16){
            unsigned af[4], bfm[4];
            ldsm4(af, sptr(As + (16*wr4+rl)*520 + ks + ca));
            ldsm4(bfm, sptr(Ws + (wc*16+rb)*520 + ks + cb));
            mma16(acc[0], af, &bfm[0]);
            mma16(acc[1], af, &bfm[2]);
        }
        #pragma unroll
        for (int nf=0;nf<2;nf++){
            int col = wc*16 + nf*8 + 2*t4;
            Gs[(16*wr4+g)*34 + col]   = acc[nf][0];
            Gs[(16*wr4+g)*34 + col+1] = acc[nf][1];
            Gs[(16*wr4+g+8)*34 + col]   = acc[nf][2];
            Gs[(16*wr4+g+8)*34 + col+1] = acc[nf][3];
        }
        __syncthreads();
        #pragma unroll
        for (int k=0;k<2;k++){
            int p = tid*2 + k;
            int row = p>>3, q = p&7;
            int h = h0 + q;
            int dir = row>>5, b = row&31;
            const float* xb = d_Xe + (long)(t*ROWS_E + row)*GG;
            float gi = Gs[row*34 + 4*q + 0] + xb[h];
            float gf = Gs[row*34 + 4*q + 1] + xb[HH+h];
            float g2 = Gs[row*34 + 4*q + 2] + xb[2*HH+h];
            float go = Gs[row*34 + 4*q + 3] + xb[3*HH+h];
            cst[k] = sigm(gf)*cst[k] + sigm(gi)*tanhf(g2);
            float hn = sigm(go)*tanhf(cst[k]);
            bf16 hb16 = __float2bfloat16_rn(hn);
            d_HencB[((long)(dir*(TT+1)+(t+1))*BB + b)*HH + h] = hb16;
            // fused decoder init: decoder row = dir*2048 + t*32 + b
            long drow = ((long)(dir*2048 + t*32 + b))*HH + h;
            d_HdecB[drow] = hb16;
            d_Cdec[drow] = __bfloat162float(hb16);
        }
        __threadfence();
        __syncthreads();
        if (tid==0){
            unsigned a = atomicAdd(&g_cnt, 1u);
            if (a == gridDim.x-1){
                g_cnt = 0;
                __threadfence();
                atomicExch(&g_gen, gen+1u);
            } else {
                while (*((volatile unsigned*)&g_gen) != gen+1u) __nanosleep(32);
                __threadfence();
            }
        }
        __syncthreads();
        gen++;
    }
}

// ----- gathered picks -----
__global__ void k_picks(const float* __restrict__ fhb, const float* __restrict__ bhb){
    int w = (blockIdx.x*blockDim.x + threadIdx.x) >> 5;
    int lane = threadIdx.x & 31;
    if (w >= 6*NDROW) return;
    int kind = w / NDROW;
    int row  = w % NDROW;
    int dir = row>>11, rr = row&2047, m = rr>>5, b = rr&31;
    const bf16* hW = dir ? d_hWbB : d_hWfB;
    const float* hb = dir ? bhb : fhb;
    int s, y;
    if (kind < 3){ s = kind;   y = d_tokD[dir*PDROWS + min(m+s, TT-1)*BB + b]; }
    else         { s = kind-2; y = 0; }
    const bf16* h = d_HdecB + (long)(s+1)*NDROW*HH + (long)row*HH;
    const bf16* wv = hW + (long)y*HH;
    float sum = 0.f;
    #pragma unroll 4
    for (int k=lane*2; k<HH; k+=64){
        __nv_bfloat162 a = *(const __nv_bfloat162*)(h+k);
        __nv_bfloat162 x = *(const __nv_bfloat162*)(wv+k);
        sum += __bfloat162float(a.x)*__bfloat162float(x.x)
             + __bfloat162float(a.y)*__bfloat162float(x.y);
    }
    #pragma unroll
    for (int off=16; off; off>>=1) sum += __shfl_xor_sync(0xffffffffu, sum, off);
    if (!lane){
        if (kind < 3) d_zc[s*NDROW + row] = sum + hb[y];
        else          d_zt[s*NDROW + row] = sum + hb[0];
    }
}

// ----- combine LSE partials -----
__global__ void k_lse2(){
    int i = blockIdx.x*blockDim.x + threadIdx.x;
    if (i >= SR) return;
    float mx = NEGF, sm = 0.f;
    for (int nb=0; nb<NP2; nb++){
        float2 p = *(float2*)&d_part[((long)nb*SR + i)*2];
        if (p.x > mx){ sm = sm*__expf(mx-p.x) + p.y; mx = p.x; }
        else sm += p.y*__expf(p.x-mx);
    }
    d_lse[i] = mx + logf(sm);
}

// ----- segment scores -----
__global__ void k_res(){
    int i = blockIdx.x*blockDim.x + threadIdx.x;
    if (i >= NDROW) return;
    int dir = i>>11, rr = i&2047, m = rr>>5, b = rr&31;
    float cum = 0.f;
    #pragma unroll
    for (int l=0; l<WW; l++){
        cum += d_zc[l*NDROW+i] - d_lse[l*NDROW+i];
        float tg = d_zt[(l+1)*NDROW+i] - d_lse[(l+1)*NDROW+i];
        d_res[((dir*TT+m)*WW+l)*BB + b] = cum + tg;
    }
}

// ----- final DP -----
__global__ void k_final(float* __restrict__ out){
    int b = threadIdx.x;
    float w0 = 0.f, w1 = NEGF, w2 = NEGF;
    for (int e=0; e<TT; e++){
        float p[3];
        #pragma unroll
        for (int l=0; l<3; l++){
            int st = e - l;
            p[l] = (st >= 0) ? (d_res[((0*TT+st)*WW+l)*BB + b]
                              + d_res[((1*TT+(TT-1-e))*WW+l)*BB + b]) : NEGF;
        }
        float x0 = w0+p[0], x1 = w1+p[1], x2 = w2+p[2];
        float m = fmaxf(x0, fmaxf(x1, x2));
        float tot = m + logf(__expf(x0-m) + __expf(x1-m) + __expf(x2-m));
        w2 = w1; w1 = w0; w0 = tot;
    }
    float v = w0;
    #pragma unroll
    for (int off=16; off; off>>=1) v += __shfl_xor_sync(0xffffffffu, v, off);
    if (b == 0) out[0] = -v/(float)BB;
}

extern "C" void kernel_launch(void* const* d_in, const int* in_sizes, int n_in,
                              void* d_out, int out_size){
    const int*   sent = (const int*)  d_in[0];
    const float* emb  = (const float*)d_in[1];
    const float* eWih = (const float*)d_in[2];
    const float* eWhh = (const float*)d_in[3];
    const float* eB   = (const float*)d_in[4];
    const float* fWih = (const float*)d_in[5];
    const float* fWhh = (const float*)d_in[6];
    const float* fB   = (const float*)d_in[7];
    const float* fhW  = (const float*)d_in[8];
    const float* fhb  = (const float*)d_in[9];
    const float* bWih = (const float*)d_in[10];
    const float* bWhh = (const float*)d_in[11];
    const float* bB   = (const float*)d_in[12];
    const float* bhW  = (const float*)d_in[13];
    const float* bhb  = (const float*)d_in[14];
    float* out = (float*)d_out;

    cudaFuncSetAttribute(k_enc, cudaFuncAttributeMaxDynamicSharedMemorySize, ESM_BYTES);
    cudaFuncSetAttribute(k_bgemm<0>, cudaFuncAttributeMaxDynamicSharedMemorySize, BG_SMEM);
    cudaFuncSetAttribute(k_bgemm<1>, cudaFuncAttributeMaxDynamicSharedMemorySize, BG_SMEM);
    cudaFuncSetAttribute(k_bgemm<2>, cudaFuncAttributeMaxDynamicSharedMemorySize, BG_SMEM);

    k_init<<<128,256>>>(sent);
    {
        long nA = (long)VV*EE + 3L*GG*EE;
        long nB = 2L*GG*HH + 2L*VV*HH;
        k_convA<<<(int)((nA/4+255)/256),256>>>(emb, eWih, fWih, bWih);
        k_convB<<<(int)((nB/4+255)/256),256>>>(fWhh, bWhh, fhW, bhW);
    }
    k_bgemm<0><<<dim3(16,32,1),512,BG_SMEM>>>(eB, eB, 0, 1<<30, 0);
    k_bgemm<0><<<dim3(16,34,1),512,BG_SMEM>>>(fB, bB, 1, PDROWS, 0);
    k_enc<<<64,256,ESM_BYTES>>>(eWhh);
    for (int s=0; s<4; s++)
        k_bgemm<1><<<dim3(16,32,1),512,BG_SMEM>>>(0, 0, 0, 2048, s);
    k_picks<<<3072,256>>>(fhb, bhb);
    k_bgemm<2><<<dim3(63,32,4),512,BG_SMEM>>>(fhb, bhb, 0, 2048, 0);
    k_lse2<<<64,256>>>();
    k_res<<<16,256>>>();
    k_final<<<1,32>>>(out);
}

// round 17
// speedup vs baseline: 1.1615x; 1.0090x over previous
#include <cuda_runtime.h>
#include <cuda_bf16.h>
#include <stdint.h>
#include <math.h>

#define BB 32
#define TT 64
#define VV 8000
#define EE 256
#define HH 512
#define GG 2048
#define WW 3
#define NEGF (-1e30f)
#define NDROW 4096
#define ROWS_E 64
#define PDT 68
#define PDROWS (PDT*BB)      // 2176
#define NP2 63
#define SR (4*NDROW)

typedef __nv_bfloat16 bf16;

// ----- scratch -----
__device__ float d_Xe[TT*ROWS_E*GG];
__device__ float d_Pd[2*PDROWS*GG];
__device__ float d_Cdec[2*NDROW*HH];
__device__ int   d_tokE[TT*ROWS_E];
__device__ int   d_tokD[2*PDROWS];
__device__ float d_zc[3*NDROW];
__device__ float d_zt[4*NDROW];
__device__ float d_part[NP2*SR*2];
__device__ float d_lse[4*NDROW];
__device__ float d_res[2*TT*WW*BB];
__device__ unsigned g_cnt;
__device__ unsigned g_gen;

// ----- bf16 mirrors -----
__device__ bf16 d_embB[VV*EE];
__device__ bf16 d_WeIB[GG*EE];
__device__ bf16 d_WfIB[GG*EE];
__device__ bf16 d_WbIB[GG*EE];
__device__ bf16 d_WfHB[GG*HH];
__device__ bf16 d_WbHB[GG*HH];
__device__ bf16 d_hWfB[VV*HH];
__device__ bf16 d_hWbB[VV*HH];
__device__ bf16 d_HencB[2*(TT+1)*BB*HH];
__device__ bf16 d_HdecB[5*NDROW*HH];

__device__ __forceinline__ float sigm(float x){ return 1.f/(1.f+__expf(-x)); }
__device__ __forceinline__ unsigned sptr(const void* p){
    return (unsigned)__cvta_generic_to_shared(p);
}
__device__ __forceinline__ void ldsm4(unsigned* r, unsigned a){
    asm volatile("ldmatrix.sync.aligned.m8n8.x4.shared.b16 {%0,%1,%2,%3}, [%4];\n"
        : "=r"(r[0]),"=r"(r[1]),"=r"(r[2]),"=r"(r[3]) : "r"(a));
}
__device__ __forceinline__ void mma16(float* c, const unsigned* a, const unsigned* b){
    asm volatile("mma.sync.aligned.m16n8k16.row.col.f32.bf16.bf16.f32 "
        "{%0,%1,%2,%3},{%4,%5,%6,%7},{%8,%9},{%0,%1,%2,%3};\n"
        : "+f"(c[0]),"+f"(c[1]),"+f"(c[2]),"+f"(c[3])
        : "r"(a[0]),"r"(a[1]),"r"(a[2]),"r"(a[3]),"r"(b[0]),"r"(b[1]));
}
__device__ __forceinline__ void cp16(unsigned dst, const void* src, int ssz){
    asm volatile("cp.async.cg.shared.global [%0], [%1], 16, %2;\n"
        :: "r"(dst), "l"(src), "r"(ssz));
}

// ----- fp32 -> bf16 conversion -----
__global__ void k_convA(const float* __restrict__ emb, const float* __restrict__ eWih,
                        const float* __restrict__ fWih, const float* __restrict__ bWih){
    const long n0 = (long)VV*EE, n1 = n0 + (long)GG*EE, n2 = n1 + (long)GG*EE, n3 = n2 + (long)GG*EE;
    long i = ((long)blockIdx.x*blockDim.x + threadIdx.x)*4;
    if (i >= n3) return;
    const float* src; bf16* dst; long off;
    if (i < n0){ src=emb; dst=d_embB; off=i; }
    else if (i < n1){ src=eWih; dst=d_WeIB; off=i-n0; }
    else if (i < n2){ src=fWih; dst=d_WfIB; off=i-n1; }
    else { src=bWih; dst=d_WbIB; off=i-n2; }
    float4 v = *(const float4*)(src+off);
    *(__nv_bfloat162*)(dst+off)   = __floats2bfloat162_rn(v.x, v.y);
    *(__nv_bfloat162*)(dst+off+2) = __floats2bfloat162_rn(v.z, v.w);
}
__global__ void k_convB(const float* __restrict__ fWhh, const float* __restrict__ bWhh,
                        const float* __restrict__ fhW, const float* __restrict__ bhW){
    const long n0 = (long)GG*HH, n1 = n0 + (long)GG*HH, n2 = n1 + (long)VV*HH, n3 = n2 + (long)VV*HH;
    long i = ((long)blockIdx.x*blockDim.x + threadIdx.x)*4;
    if (i >= n3) return;
    const float* src; bf16* dst; long off;
    if (i < n0){ src=fWhh; dst=d_WfHB; off=i; }
    else if (i < n1){ src=bWhh; dst=d_WbHB; off=i-n0; }
    else if (i < n2){ src=fhW; dst=d_hWfB; off=i-n1; }
    else { src=bhW; dst=d_hWbB; off=i-n2; }
    float4 v = *(const float4*)(src+off);
    *(__nv_bfloat162*)(dst+off)   = __floats2bfloat162_rn(v.x, v.y);
    *(__nv_bfloat162*)(dst+off+2) = __floats2bfloat162_rn(v.z, v.w);
}

// ----- init -----
__global__ void k_init(const int* __restrict__ sent){
    int i = blockIdx.x*blockDim.x + threadIdx.x;
    if (i == 0){ g_cnt = 0u; g_gen = 0u; }
    if (i < 2*BB*HH){
        int dir = i/(BB*HH); int rem = i%(BB*HH);
        d_HencB[(dir*(TT+1))*BB*HH + rem] = __float2bfloat16(0.f);
    }
    if (i < TT*ROWS_E){
        int t = i/ROWS_E, r = i%ROWS_E, dir = r/BB, b = r%BB;
        int tok = (t==0) ? 0 : (dir ? sent[b*TT + (TT-t)] : sent[b*TT + (t-1)]);
        d_tokE[i] = tok;
    }
    if (i < 2*PDROWS){
        int dir = i/PDROWS; int rem = i%PDROWS; int t = rem/BB, b = rem%BB;
        int tok = (t < TT) ? (dir ? sent[b*TT + (TT-1-t)] : sent[b*TT + t]) : 0;
        d_tokD[i] = tok;
    }
}

// ===================== bf16 mma.sync GEMM: 512 threads, 16 warps, warp-tile 32x32 =====================
// MODE 0: A=embB[tok], K=256, out Xe (+bias)         (encoder proj only now)
// MODE 1: A=HdecB[s],  K=512, gate-interleaved B; fused LSTM cell epilogue
// MODE 2: A=HdecB[s+1],K=512, fused partial LSE with in-CTA wn-combine
#define BG_SMEM (6*5120*2)     // 61440
extern __shared__ bf16 dynsm[];

template<int MODE>
__global__ void __launch_bounds__(512,2) k_bgemm(
    const float* __restrict__ bias0, const float* __restrict__ bias1,
    int gsel, int mhalf, int s)
{
    constexpr int KD = (MODE==0)? EE : HH;
    constexpr int NC = KD/32;
    bf16* sA = dynsm;
    bf16* sB = dynsm + 3*5120;
    const int tid = threadIdx.x;
    const int m0 = blockIdx.y*128, n0 = blockIdx.x*128;
    const int ss = (MODE==2)? (int)blockIdx.z : s;
    const int dir = (m0 >= mhalf)? 1 : 0;
    const bf16* Bm;
    if (MODE==0) Bm = gsel? (dir? d_WbIB : d_WfIB) : d_WeIB;
    else if (MODE==1) Bm = dir? d_WbHB : d_WfHB;
    else Bm = dir? d_hWbB : d_hWfB;
    const float* bias = dir? bias1 : bias0;

    const int lrow = tid>>2, lc = (tid&3)*8;
    const bf16* arow;
    if (MODE==0){
        const int* tok = gsel? d_tokD : d_tokE;
        arow = d_embB + (long)tok[m0+lrow]*KD;
    } else if (MODE==1){
        arow = d_HdecB + (long)ss*NDROW*HH + (long)(m0+lrow)*HH;
    } else {
        arow = d_HdecB + (long)(ss+1)*NDROW*HH + (long)(m0+lrow)*HH;
    }
    const int vrow = n0 + lrow;
    const bool bval = (MODE!=2) || (vrow < VV);
    long browi;
    if (MODE==1){
        int gate = (vrow>>5)&3, hsub = vrow&31;
        browi = (long)gate*HH + (long)blockIdx.x*32 + hsub;
    } else {
        browi = (long)(bval? vrow : 0);
    }
    const bf16* brow = Bm + browi*KD;
    const int bok = bval? 16 : 0;

    const unsigned smA = sptr(sA), smB = sptr(sB);
    const unsigned ldoff = (unsigned)((lrow*40 + lc)*2);

    auto issue_chunk = [&](int kt, int st){
        int k0 = kt*32;
        cp16(smA + (unsigned)st*10240u + ldoff, arow + k0 + lc, 16);
        cp16(smB + (unsigned)st*10240u + ldoff, brow + k0 + lc, bok);
        asm volatile("cp.async.commit_group;" ::: "memory");
    };

    const int lane = tid&31, warp = tid>>5;
    const int wm = warp&3, wn = warp>>2;
    const int g = lane>>2, t4 = lane&3;
    const int rl = (lane&7) + ((lane>>3)&1)*8;
    const int ca = (lane>>4)*8;
    const int rb = (lane&7) + ((lane>>4)&1)*8;
    const int cb = ((lane>>3)&1)*8;

    float acc[2][4][4];
    #pragma unroll
    for (int i=0;i<2;i++)
        #pragma unroll
        for (int j=0;j<4;j++)
            #pragma unroll
            for (int e=0;e<4;e++) acc[i][j][e]=0.f;

    issue_chunk(0, 0);
    issue_chunk(1, 1);

    #pragma unroll 1
    for (int kt=0; kt<NC; kt++){
        asm volatile("cp.async.wait_group 1;" ::: "memory");
        __syncthreads();
        int nx = kt + 2;
        if (nx < NC) issue_chunk(nx, nx%3);
        else asm volatile("cp.async.commit_group;" ::: "memory");
        const bf16* Ab = sA + (kt%3)*5120;
        const bf16* Bb = sB + (kt%3)*5120;
        #pragma unroll
        for (int ks=0; ks<32; ks+=16){
            unsigned af[2][4], bfm[2][4];
            #pragma unroll
            for (int mf=0;mf<2;mf++)
                ldsm4(af[mf], sptr(Ab + (wm*32+mf*16+rl)*40 + ks + ca));
            #pragma unroll
            for (int p=0;p<2;p++)
                ldsm4(bfm[p], sptr(Bb + (wn*32+p*16+rb)*40 + ks + cb));
            #pragma unroll
            for (int mf=0;mf<2;mf++)
                #pragma unroll
                for (int nf=0;nf<4;nf++)
                    mma16(acc[mf][nf], af[mf], &bfm[nf>>1][(nf&1)*2]);
        }
    }

    if (MODE==0){
        float* Co = gsel? d_Pd : d_Xe;
        #pragma unroll
        for (int mf=0; mf<2; mf++)
            #pragma unroll
            for (int lohi=0; lohi<2; lohi++){
                int r = m0 + wm*32 + mf*16 + g + lohi*8;
                #pragma unroll
                for (int nf=0; nf<4; nf++){
                    int col = n0 + wn*32 + nf*8 + 2*t4;
                    float2 o;
                    o.x = acc[mf][nf][lohi*2+0] + bias[col];
                    o.y = acc[mf][nf][lohi*2+1] + bias[col+1];
                    *(float2*)&Co[(long)r*GG + col] = o;
                }
            }
    } else if (MODE==1){
        __syncthreads();
        bf16* Gsm = dynsm;                    // [128][132]
        #pragma unroll
        for (int mf=0; mf<2; mf++)
            #pragma unroll
            for (int lohi=0; lohi<2; lohi++){
                int lr = wm*32 + mf*16 + g + lohi*8;
                int row = m0 + lr;
                int rr = row - dir*2048;
                int m = rr>>5, b2 = rr&31;
                int tp = (ss==0)? TT : min(m+ss-1, TT-1);
                const float* xr = d_Pd + ((long)(dir*PDT+tp)*BB + b2)*GG
                                + (long)wn*HH + (long)blockIdx.x*32;
                #pragma unroll
                for (int nf=0; nf<4; nf++){
                    int cs = nf*8 + 2*t4;
                    float gx = acc[mf][nf][lohi*2+0] + xr[cs];
                    float gy = acc[mf][nf][lohi*2+1] + xr[cs+1];
                    *(__nv_bfloat162*)&Gsm[lr*132 + wn*32 + cs] = __floats2bfloat162_rn(gx, gy);
                }
            }
        __syncthreads();
        #pragma unroll
        for (int k=0; k<8; k++){
            int p = tid*8 + k;
            int lr = p>>5, hsub = p&31;
            int row = m0 + lr;
            int h = blockIdx.x*32 + hsub;
            float gi = __bfloat162float(Gsm[lr*132 +  0 + hsub]);
            float gf = __bfloat162float(Gsm[lr*132 + 32 + hsub]);
            float g2 = __bfloat162float(Gsm[lr*132 + 64 + hsub]);
            float go = __bfloat162float(Gsm[lr*132 + 96 + hsub]);
            long ci = (long)row*HH + h;
            float cp = d_Cdec[(ss&1)*NDROW*HH + ci];
            float c = sigm(gf)*cp + sigm(gi)*tanhf(g2);
            float hn = sigm(go)*tanhf(c);
            d_Cdec[((ss+1)&1)*NDROW*HH + ci] = c;
            d_HdecB[(long)(ss+1)*NDROW*HH + ci] = __float2bfloat16_rn(hn);
        }
    } else {
        __syncthreads();
        float2* buf = (float2*)dynsm;         // [128][4]
        #pragma unroll
        for (int mf=0; mf<2; mf++)
            #pragma unroll
            for (int lohi=0; lohi<2; lohi++){
                int lr = wm*32 + mf*16 + g + lohi*8;
                float z[8]; float mx = NEGF;
                #pragma unroll
                for (int nf=0; nf<4; nf++)
                    #pragma unroll
                    for (int e=0; e<2; e++){
                        int v = n0 + wn*32 + nf*8 + 2*t4 + e;
                        float zz = acc[mf][nf][lohi*2+e] + ((v<VV)? bias[v] : NEGF);
                        z[nf*2+e] = zz;
                        mx = fmaxf(mx, zz);
                    }
                mx = fmaxf(mx, __shfl_xor_sync(0xffffffffu, mx, 1));
                mx = fmaxf(mx, __shfl_xor_sync(0xffffffffu, mx, 2));
                float sm = 0.f;
                #pragma unroll
                for (int j=0;j<8;j++) sm += __expf(z[j]-mx);
                sm += __shfl_xor_sync(0xffffffffu, sm, 1);
                sm += __shfl_xor_sync(0xffffffffu, sm, 2);
                if (t4 == 0){
                    bool valid = (n0 + wn*32) < VV;
                    buf[lr*4 + wn] = valid? make_float2(mx, sm) : make_float2(NEGF, 0.f);
                }
            }
        __syncthreads();
        if (tid < 128){
            int lr = tid;
            float mx = NEGF, sv = 0.f;
            #pragma unroll
            for (int j=0;j<4;j++){
                float2 p = buf[lr*4+j];
                if (p.x > mx){ sv = sv*__expf(mx-p.x) + p.y; mx = p.x; }
                else sv += p.y*__expf(p.x-mx);
            }
            long srow = (long)ss*NDROW + m0 + lr;
            d_part[((long)blockIdx.x*SR + srow)*2    ] = mx;
            d_part[((long)blockIdx.x*SR + srow)*2 + 1] = sv;
        }
    }
}

// ===================== fused: persistent encoder (blocks 0..63) + decoder proj (blocks 64..607) =====================
// enc smem: Ws[32][520] bf16 + As[64][520] bf16 + Gs[64][34] f32 = 108544 B
// proj smem: 4-stage 256-thread GEMM = 81920 B (fits inside)
#define ESM_BYTES (32*520*2 + 64*520*2 + 64*34*4)
#define ENC_BLKS 64
#define PROJ_BLKS (34*16)
__global__ void __launch_bounds__(256) k_enc(const float* __restrict__ Whh,
                                             const float* __restrict__ fB,
                                             const float* __restrict__ bB2){
    extern __shared__ char esm[];
    const int tid = threadIdx.x;

    if (blockIdx.x >= ENC_BLKS){
        // ---------- decoder input proj: 256 threads, 8 warps, 4-stage cp.async ----------
        bf16* sA = (bf16*)esm;                // [4][128*40]
        bf16* sB = sA + 4*5120;               // [4][128*40]
        const int bid = blockIdx.x - ENC_BLKS;
        const int m0 = (bid % 34)*128, n0 = (bid / 34)*128;
        const int dir = (m0 >= PDROWS)? 1 : 0;
        const bf16* Bm = dir? d_WbIB : d_WfIB;
        const float* bias = dir? bB2 : fB;

        const int lrow = tid>>1, lc = (tid&1)*16;
        const bf16* arow = d_embB + (long)d_tokD[m0+lrow]*EE;
        const bf16* brow = Bm + (long)(n0+lrow)*EE;

        const unsigned smA = sptr(sA), smB = sptr(sB);
        const unsigned ldoff = (unsigned)(lrow*80 + (tid&1)*32);

        auto issue_chunk = [&](int kt, int st){
            int k0 = kt*32;
            unsigned adst = smA + (unsigned)st*10240u + ldoff;
            cp16(adst,      arow + k0 + lc,     16);
            cp16(adst+16u,  arow + k0 + lc + 8, 16);
            unsigned bdst = smB + (unsigned)st*10240u + ldoff;
            cp16(bdst,      brow + k0 + lc,     16);
            cp16(bdst+16u,  brow + k0 + lc + 8, 16);
            asm volatile("cp.async.commit_group;" ::: "memory");
        };

        const int lane = tid&31, warp = tid>>5;
        const int wm = warp&1, wn = warp>>1;
        const int g = lane>>2, t4 = lane&3;
        const int rl = (lane&7) + ((lane>>3)&1)*8;
        const int ca = (lane>>4)*8;
        const int rb = (lane&7) + ((lane>>4)&1)*8;
        const int cb = ((lane>>3)&1)*8;

        float acc[4][4][4];
        #pragma unroll
        for (int i=0;i<4;i++)
            #pragma unroll
            for (int j=0;j<4;j++)
                #pragma unroll
                for (int e=0;e<4;e++) acc[i][j][e]=0.f;

        issue_chunk(0, 0);
        issue_chunk(1, 1);
        issue_chunk(2, 2);

        #pragma unroll 1
        for (int kt=0; kt<8; kt++){
            asm volatile("cp.async.wait_group 2;" ::: "memory");
            __syncthreads();
            int nx = kt + 3;
            if (nx < 8) issue_chunk(nx, nx&3);
            else asm volatile("cp.async.commit_group;" ::: "memory");
            const bf16* Ab = sA + (kt&3)*5120;
            const bf16* Bb = sB + (kt&3)*5120;
            #pragma unroll
            for (int ks=0; ks<32; ks+=16){
                unsigned af[4][4], bfm[2][4];
                #pragma unroll
                for (int mf=0;mf<4;mf++)
                    ldsm4(af[mf], sptr(Ab + (wm*64+mf*16+rl)*40 + ks + ca));
                #pragma unroll
                for (int p=0;p<2;p++)
                    ldsm4(bfm[p], sptr(Bb + (wn*32+p*16+rb)*40 + ks + cb));
                #pragma unroll
                for (int mf=0;mf<4;mf++)
                    #pragma unroll
                    for (int nf=0;nf<4;nf++)
                        mma16(acc[mf][nf], af[mf], &bfm[nf>>1][(nf&1)*2]);
            }
        }
        #pragma unroll
        for (int mf=0; mf<4; mf++)
            #pragma unroll
            for (int lohi=0; lohi<2; lohi++){
                int r = m0 + wm*64 + mf*16 + g + lohi*8;
                #pragma unroll
                for (int nf=0; nf<4; nf++){
                    int col = n0 + wn*32 + nf*8 + 2*t4;
                    float2 o;
                    o.x = acc[mf][nf][lohi*2+0] + bias[col];
                    o.y = acc[mf][nf][lohi*2+1] + bias[col+1];
                    *(float2*)&d_Pd[(long)r*GG + col] = o;
                }
            }
        return;
    }

    // ---------- persistent encoder ----------
    bf16* Ws  = (bf16*)esm;
    bf16* As  = Ws + 32*520;
    float* Gs = (float*)(As + 64*520);
    const int h0 = blockIdx.x*8;

    {
        int c = tid>>3, t8 = tid&7;
        int gg = c&3, q = c>>2;
        const float* wr = Whh + (long)(gg*HH + h0 + q)*HH + t8*64;
        bf16* dst = Ws + c*520 + t8*64;
        #pragma unroll 4
        for (int j=0;j<64;j+=4){
            float4 v = *(const float4*)(wr+j);
            dst[j]   = __float2bfloat16_rn(v.x);
            dst[j+1] = __float2bfloat16_rn(v.y);
            dst[j+2] = __float2bfloat16_rn(v.z);
            dst[j+3] = __float2bfloat16_rn(v.w);
        }
    }
    __syncthreads();

    const int lane = tid&31, warp = tid>>5;
    const int wr4 = warp&3, wc = warp>>2;
    const int g = lane>>2, t4 = lane&3;
    const int rl = (lane&7) + ((lane>>3)&1)*8;
    const int ca = (lane>>4)*8;
    const int rb = (lane&7) + ((lane>>4)&1)*8;
    const int cb = ((lane>>3)&1)*8;
    const int srow = tid>>2, qd = tid&3;
    const int sdir = srow>>5, sb = srow&31;

    const unsigned asbase = sptr(As) + (unsigned)((srow*520 + qd*128)*2);

    float cst[2] = {0.f,0.f};
    unsigned gen = 0;

    for (int t=0; t<TT; t++){
        // split-K staging: qd<2 threads hold K<256, wait immediately; qd>=2 overlap
        {
            const bf16* src = d_HencB + ((long)(sdir*(TT+1)+t)*BB + sb)*HH + qd*128;
            #pragma unroll
            for (int i=0;i<16;i++) cp16(asbase + i*16u, src + i*8, 16);
            asm volatile("cp.async.commit_group;" ::: "memory");
            if (qd < 2) asm volatile("cp.async.wait_group 0;" ::: "memory");
        }
        __syncthreads();

        float acc[2][4];
        #pragma unroll
        for (int nf=0;nf<2;nf++)
            #pragma unroll
            for (int e=0;e<4;e++) acc[nf][e]=0.f;

        // first K half (0..255) while second half streams in
        #pragma unroll 4
        for (int ks=0; ks<256; ks+=16){
            unsigned af[4], bfm[4];
            ldsm4(af, sptr(As + (16*wr4+rl)*520 + ks + ca));
            ldsm4(bfm, sptr(Ws + (wc*16+rb)*520 + ks + cb));
            mma16(acc[0], af, &bfm[0]);
            mma16(acc[1], af, &bfm[2]);
        }
        if (qd >= 2) asm volatile("cp.async.wait_group 0;" ::: "memory");
        __syncthreads();
        #pragma unroll 4
        for (int ks=256; ks<512; ks+=16){
            unsigned af[4], bfm[4];
            ldsm4(af, sptr(As + (16*wr4+rl)*520 + ks + ca));
            ldsm4(bfm, sptr(Ws + (wc*16+rb)*520 + ks + cb));
            mma16(acc[0], af, &bfm[0]);
            mma16(acc[1], af, &bfm[2]);
        }
        #pragma unroll
        for (int nf=0;nf<2;nf++){
            int col = wc*16 + nf*8 + 2*t4;
            Gs[(16*wr4+g)*34 + col]   = acc[nf][0];
            Gs[(16*wr4+g)*34 + col+1] = acc[nf][1];
            Gs[(16*wr4+g+8)*34 + col]   = acc[nf][2];
            Gs[(16*wr4+g+8)*34 + col+1] = acc[nf][3];
        }
        __syncthreads();
        #pragma unroll
        for (int k=0;k<2;k++){
            int p = tid*2 + k;
            int row = p>>3, q = p&7;
            int h = h0 + q;
            int dir = row>>5, b = row&31;
            const float* xb = d_Xe + (long)(t*ROWS_E + row)*GG;
            float gi = Gs[row*34 + 4*q + 0] + xb[h];
            float gf = Gs[row*34 + 4*q + 1] + xb[HH+h];
            float g2 = Gs[row*34 + 4*q + 2] + xb[2*HH+h];
            float go = Gs[row*34 + 4*q + 3] + xb[3*HH+h];
            cst[k] = sigm(gf)*cst[k] + sigm(gi)*tanhf(g2);
            float hn = sigm(go)*tanhf(cst[k]);
            bf16 hb16 = __float2bfloat16_rn(hn);
            d_HencB[((long)(dir*(TT+1)+(t+1))*BB + b)*HH + h] = hb16;
            long drow = ((long)(dir*2048 + t*32 + b))*HH + h;
            d_HdecB[drow] = hb16;
            d_Cdec[drow] = __bfloat162float(hb16);
        }
        __threadfence();
        __syncthreads();
        if (tid==0){
            unsigned a = atomicAdd(&g_cnt, 1u);
            if (a == ENC_BLKS-1){
                g_cnt = 0;
                __threadfence();
                atomicExch(&g_gen, gen+1u);
            } else {
                while (*((volatile unsigned*)&g_gen) != gen+1u) __nanosleep(32);
                __threadfence();
            }
        }
        __syncthreads();
        gen++;
    }
}

// ----- gathered picks -----
__global__ void k_picks(const float* __restrict__ fhb, const float* __restrict__ bhb){
    int w = (blockIdx.x*blockDim.x + threadIdx.x) >> 5;
    int lane = threadIdx.x & 31;
    if (w >= 6*NDROW) return;
    int kind = w / NDROW;
    int row  = w % NDROW;
    int dir = row>>11, rr = row&2047, m = rr>>5, b = rr&31;
    const bf16* hW = dir ? d_hWbB : d_hWfB;
    const float* hb = dir ? bhb : fhb;
    int s, y;
    if (kind < 3){ s = kind;   y = d_tokD[dir*PDROWS + min(m+s, TT-1)*BB + b]; }
    else         { s = kind-2; y = 0; }
    const bf16* h = d_HdecB + (long)(s+1)*NDROW*HH + (long)row*HH;
    const bf16* wv = hW + (long)y*HH;
    float sum = 0.f;
    #pragma unroll 4
    for (int k=lane*2; k<HH; k+=64){
        __nv_bfloat162 a = *(const __nv_bfloat162*)(h+k);
        __nv_bfloat162 x = *(const __nv_bfloat162*)(wv+k);
        sum += __bfloat162float(a.x)*__bfloat162float(x.x)
             + __bfloat162float(a.y)*__bfloat162float(x.y);
    }
    #pragma unroll
    for (int off=16; off; off>>=1) sum += __shfl_xor_sync(0xffffffffu, sum, off);
    if (!lane){
        if (kind < 3) d_zc[s*NDROW + row] = sum + hb[y];
        else          d_zt[s*NDROW + row] = sum + hb[0];
    }
}

// ----- combine LSE partials -----
__global__ void k_lse2(){
    int i = blockIdx.x*blockDim.x + threadIdx.x;
    if (i >= SR) return;
    float mx = NEGF, sm = 0.f;
    for (int nb=0; nb<NP2; nb++){
        float2 p = *(float2*)&d_part[((long)nb*SR + i)*2];
        if (p.x > mx){ sm = sm*__expf(mx-p.x) + p.y; mx = p.x; }
        else sm += p.y*__expf(p.x-mx);
    }
    d_lse[i] = mx + logf(sm);
}

// ----- segment scores -----
__global__ void k_res(){
    int i = blockIdx.x*blockDim.x + threadIdx.x;
    if (i >= NDROW) return;
    int dir = i>>11, rr = i&2047, m = rr>>5, b = rr&31;
    float cum = 0.f;
    #pragma unroll
    for (int l=0; l<WW; l++){
        cum += d_zc[l*NDROW+i] - d_lse[l*NDROW+i];
        float tg = d_zt[(l+1)*NDROW+i] - d_lse[(l+1)*NDROW+i];
        d_res[((dir*TT+m)*WW+l)*BB + b] = cum + tg;
    }
}

// ----- final DP -----
__global__ void k_final(float* __restrict__ out){
    int b = threadIdx.x;
    float w0 = 0.f, w1 = NEGF, w2 = NEGF;
    for (int e=0; e<TT; e++){
        float p[3];
        #pragma unroll
        for (int l=0; l<3; l++){
            int st = e - l;
            p[l] = (st >= 0) ? (d_res[((0*TT+st)*WW+l)*BB + b]
                              + d_res[((1*TT+(TT-1-e))*WW+l)*BB + b]) : NEGF;
        }
        float x0 = w0+p[0], x1 = w1+p[1], x2 = w2+p[2];
        float m = fmaxf(x0, fmaxf(x1, x2));
        float tot = m + logf(__expf(x0-m) + __expf(x1-m) + __expf(x2-m));
        w2 = w1; w1 = w0; w0 = tot;
    }
    float v = w0;
    #pragma unroll
    for (int off=16; off; off>>=1) v += __shfl_xor_sync(0xffffffffu, v, off);
    if (b == 0) out[0] = -v/(float)BB;
}

extern "C" void kernel_launch(void* const* d_in, const int* in_sizes, int n_in,
                              void* d_out, int out_size){
    const int*   sent = (const int*)  d_in[0];
    const float* emb  = (const float*)d_in[1];
    const float* eWih = (const float*)d_in[2];
    const float* eWhh = (const float*)d_in[3];
    const float* eB   = (const float*)d_in[4];
    const float* fWih = (const float*)d_in[5];
    const float* fWhh = (const float*)d_in[6];
    const float* fB   = (const float*)d_in[7];
    const float* fhW  = (const float*)d_in[8];
    const float* fhb  = (const float*)d_in[9];
    const float* bWih = (const float*)d_in[10];
    const float* bWhh = (const float*)d_in[11];
    const float* bB   = (const float*)d_in[12];
    const float* bhW  = (const float*)d_in[13];
    const float* bhb  = (const float*)d_in[14];
    float* out = (float*)d_out;

    cudaFuncSetAttribute(k_enc, cudaFuncAttributeMaxDynamicSharedMemorySize, ESM_BYTES);
    cudaFuncSetAttribute(k_bgemm<0>, cudaFuncAttributeMaxDynamicSharedMemorySize, BG_SMEM);
    cudaFuncSetAttribute(k_bgemm<1>, cudaFuncAttributeMaxDynamicSharedMemorySize, BG_SMEM);
    cudaFuncSetAttribute(k_bgemm<2>, cudaFuncAttributeMaxDynamicSharedMemorySize, BG_SMEM);

    k_init<<<128,256>>>(sent);
    {
        long nA = (long)VV*EE + 3L*GG*EE;
        long nB = 2L*GG*HH + 2L*VV*HH;
        k_convA<<<(int)((nA/4+255)/256),256>>>(emb, eWih, fWih, bWih);
        k_convB<<<(int)((nB/4+255)/256),256>>>(fWhh, bWhh, fhW, bhW);
    }
    k_bgemm<0><<<dim3(16,32,1),512,BG_SMEM>>>(eB, eB, 0, 1<<30, 0);
    // fused: encoder (64 blocks) + decoder input proj (544 blocks)
    k_enc<<<ENC_BLKS+PROJ_BLKS,256,ESM_BYTES>>>(eWhh, fB, bB);
    for (int s=0; s<4; s++)
        k_bgemm<1><<<dim3(16,32,1),512,BG_SMEM>>>(0, 0, 0, 2048, s);
    k_picks<<<3072,256>>>(fhb, bhb);
    k_bgemm<2><<<dim3(63,32,4),512,BG_SMEM>>>(fhb, bhb, 0, 2048, 0);
    k_lse2<<<64,256>>>();
    k_res<<<16,256>>>();
    k_final<<<1,32>>>(out);
}